// round 1
// baseline (speedup 1.0000x reference)
#include <cuda_runtime.h>
#include <math.h>

#define NN 100000
#define HH 128
#define HD2 256

// Scratch (allocation-free rule: __device__ globals)
__device__ float g_x [(size_t)NN * HH];   // current features
__device__ float g_t [(size_t)NN * HH];   // x @ w
__device__ float g_h1[(size_t)NN * HD2];  // mlp hidden 1
__device__ float g_h2[(size_t)NN * HD2];  // mlp hidden 2
__device__ float g_s1[NN];
__device__ float g_s2[NN];

// ---------------------------------------------------------------------------
__global__ void zero_kernel(float* __restrict__ p, size_t n) {
    size_t i = (size_t)blockIdx.x * blockDim.x + threadIdx.x;
    size_t stride = (size_t)gridDim.x * blockDim.x;
    for (; i < n; i += stride) p[i] = 0.0f;
}

// SpMM: one warp per edge, 4 floats per lane, vector RED into accumulator
__global__ void spmm_kernel(const int* __restrict__ rows, const int* __restrict__ cols,
                            const float* __restrict__ vals, const float* __restrict__ xin,
                            float* __restrict__ xout, int nE) {
    long long idx = (long long)blockIdx.x * blockDim.x + threadIdx.x;
    int e = (int)(idx >> 5);
    if (e >= nE) return;
    int lane = (int)(idx & 31);
    int r = __ldg(rows + e);
    int c = __ldg(cols + e);
    float v = __ldg(vals + e);
    float4 xv = *(const float4*)(xin + (size_t)c * HH + lane * 4);
    float4 p = make_float4(xv.x * v, xv.y * v, xv.z * v, xv.w * v);
    atomicAdd((float4*)(xout + (size_t)r * HH + lane * 4), p);  // sm_90+: RED.128
}

// relu then (optionally) L2-normalize each row of [M,128]; one warp per row
__global__ void relu_norm_kernel(float* __restrict__ x, int M, int do_norm) {
    long long idx = (long long)blockIdx.x * blockDim.x + threadIdx.x;
    int row = (int)(idx >> 5);
    if (row >= M) return;
    int lane = (int)(idx & 31);
    float4* p = (float4*)(x + (size_t)row * HH) + lane;
    float4 v = *p;
    v.x = fmaxf(v.x, 0.f); v.y = fmaxf(v.y, 0.f);
    v.z = fmaxf(v.z, 0.f); v.w = fmaxf(v.w, 0.f);
    if (do_norm) {
        float ss = v.x * v.x + v.y * v.y + v.z * v.z + v.w * v.w;
        #pragma unroll
        for (int o = 16; o; o >>= 1) ss += __shfl_xor_sync(0xffffffffu, ss, o);
        float inv = 1.0f / fmaxf(sqrtf(ss), 1e-12f);
        v.x *= inv; v.y *= inv; v.z *= inv; v.w *= inv;
    }
    *p = v;
}

// Tiled SGEMM: C[M,Ncol] = A[M,K] @ B[K,Ncol] (+bias) (relu optional)
// BM=64, BN=64, BK=16, 256 threads, 4x4 micro-tile per thread
__global__ void gemm_kernel(const float* __restrict__ A, const float* __restrict__ B,
                            const float* __restrict__ bias, float* __restrict__ C,
                            int M, int K, int Ncol, int relu) {
    __shared__ float As[16][68];  // padded, transposed (k-major)
    __shared__ float Bs[16][64];
    int tid = threadIdx.x;
    int tx = tid & 15;   // col group: cols tx*4 .. tx*4+3
    int ty = tid >> 4;   // row group: rows ty*4 .. ty*4+3
    int row0 = blockIdx.x * 64;
    int col0 = blockIdx.y * 64;

    int lm = tid >> 2;            // A-load: row within tile 0..63
    int lk = (tid & 3) * 4;       //         k offset 0,4,8,12
    int lb_k = tid >> 4;          // B-load: k within tile 0..15
    int lb_n = (tid & 15) * 4;    //         col offset

    float acc[4][4] = {};
    for (int k0 = 0; k0 < K; k0 += 16) {
        int arow = row0 + lm;
        float4 av = make_float4(0.f, 0.f, 0.f, 0.f);
        if (arow < M) av = *(const float4*)(A + (size_t)arow * K + k0 + lk);
        As[lk + 0][lm] = av.x; As[lk + 1][lm] = av.y;
        As[lk + 2][lm] = av.z; As[lk + 3][lm] = av.w;
        *(float4*)&Bs[lb_k][lb_n] =
            *(const float4*)(B + (size_t)(k0 + lb_k) * Ncol + col0 + lb_n);
        __syncthreads();
        #pragma unroll
        for (int k = 0; k < 16; k++) {
            float4 a4 = *(const float4*)&As[k][ty * 4];
            float4 b4 = *(const float4*)&Bs[k][tx * 4];
            float ar[4] = {a4.x, a4.y, a4.z, a4.w};
            float br[4] = {b4.x, b4.y, b4.z, b4.w};
            #pragma unroll
            for (int i = 0; i < 4; i++)
                #pragma unroll
                for (int j = 0; j < 4; j++)
                    acc[i][j] += ar[i] * br[j];
        }
        __syncthreads();
    }
    float bv[4] = {0.f, 0.f, 0.f, 0.f};
    if (bias) {
        #pragma unroll
        for (int j = 0; j < 4; j++) bv[j] = bias[col0 + tx * 4 + j];
    }
    #pragma unroll
    for (int i = 0; i < 4; i++) {
        int row = row0 + ty * 4 + i;
        if (row >= M) continue;
        float4 v;
        v.x = acc[i][0] + bv[0]; v.y = acc[i][1] + bv[1];
        v.z = acc[i][2] + bv[2]; v.w = acc[i][3] + bv[3];
        if (relu) {
            v.x = fmaxf(v.x, 0.f); v.y = fmaxf(v.y, 0.f);
            v.z = fmaxf(v.z, 0.f); v.w = fmaxf(v.w, 0.f);
        }
        *(float4*)(C + (size_t)row * Ncol + col0 + tx * 4) = v;
    }
}

// Final MLP layer [M,256] @ [256,1] + b3, accumulated into score; warp per row
__global__ void mlp3_kernel(const float* __restrict__ h, const float* __restrict__ m3,
                            const float* __restrict__ b3, float* __restrict__ s, int M) {
    long long idx = (long long)blockIdx.x * blockDim.x + threadIdx.x;
    int row = (int)(idx >> 5);
    if (row >= M) return;
    int lane = (int)(idx & 31);
    const float4* hp = (const float4*)(h + (size_t)row * HD2);
    const float4* mp = (const float4*)m3;
    float4 a = hp[lane],      ma = mp[lane];
    float4 b = hp[lane + 32], mb = mp[lane + 32];
    float d = a.x * ma.x + a.y * ma.y + a.z * ma.z + a.w * ma.w
            + b.x * mb.x + b.y * mb.y + b.z * mb.z + b.w * mb.w;
    #pragma unroll
    for (int o = 16; o; o >>= 1) d += __shfl_xor_sync(0xffffffffu, d, o);
    if (lane == 0) s[row] += d + b3[0];
}

__global__ void mul_kernel(const float* __restrict__ a, const float* __restrict__ b,
                           float* __restrict__ out, int M) {
    int i = blockIdx.x * blockDim.x + threadIdx.x;
    if (i < M) out[i] = a[i] * b[i];
}

// ---------------------------------------------------------------------------
extern "C" void kernel_launch(void* const* d_in, const int* in_sizes, int n_in,
                              void* d_out, int out_size) {
    const int*   a1r = (const int*)d_in[0];
    const int*   a1c = (const int*)d_in[1];
    const float* a1v = (const float*)d_in[2];
    const int*   a2r = (const int*)d_in[3];
    const int*   a2c = (const int*)d_in[4];
    const float* a2v = (const float*)d_in[5];
    const float* w1  = (const float*)d_in[6];
    const float* w[8];
    for (int i = 0; i < 8; i++) w[i] = (const float*)d_in[7 + i];
    const float* m1 = (const float*)d_in[15];
    const float* b1 = (const float*)d_in[16];
    const float* m2 = (const float*)d_in[17];
    const float* b2 = (const float*)d_in[18];
    const float* m3 = (const float*)d_in[19];
    const float* b3 = (const float*)d_in[20];
    float* out = (float*)d_out;

    const int E = in_sizes[0];
    const int M = in_sizes[6] / HH;  // 100000

    float *gx, *gt, *gh1, *gh2, *gs1, *gs2;
    cudaGetSymbolAddress((void**)&gx,  g_x);
    cudaGetSymbolAddress((void**)&gt,  g_t);
    cudaGetSymbolAddress((void**)&gh1, g_h1);
    cudaGetSymbolAddress((void**)&gh2, g_h2);
    cudaGetSymbolAddress((void**)&gs1, g_s1);
    cudaGetSymbolAddress((void**)&gs2, g_s2);

    const int warpBlocks  = (int)(((long long)M * 32 + 255) / 256);
    const int spmmBlocks  = (int)(((long long)E * 32 + 255) / 256);
    const size_t xElems   = (size_t)M * HH;
    const int zeroBlocksX = (int)((xElems + 255) / 256);

    dim3 gemm_w((M + 63) / 64, HH / 64);    // [M,128]x[128,128]
    dim3 gemm_m1((M + 63) / 64, HD2 / 64);  // [M,128]x[128,256]
    dim3 gemm_m2((M + 63) / 64, HD2 / 64);  // [M,256]x[256,256]

    auto mlp = [&](const float* xin, float* s) {
        gemm_kernel<<<gemm_m1, 256>>>(xin, m1, b1, gh1, M, HH, HD2, 1);
        gemm_kernel<<<gemm_m2, 256>>>(gh1, m2, b2, gh2, M, HD2, HD2, 1);
        mlp3_kernel<<<warpBlocks, 256>>>(gh2, m3, b3, s, M);
    };

    auto branch = [&](const int* rr, const int* cc, const float* vv, float* s) {
        zero_kernel<<<(M + 255) / 256, 256>>>(s, (size_t)M);
        // layer 1: x = relu(A @ w1); normalize; score = mlp(x)
        zero_kernel<<<zeroBlocksX, 256>>>(gx, xElems);
        spmm_kernel<<<spmmBlocks, 256>>>(rr, cc, vv, w1, gx, E);
        relu_norm_kernel<<<warpBlocks, 256>>>(gx, M, 1);
        mlp(gx, s);
        // layers 2..9
        for (int i = 0; i < 8; i++) {
            gemm_kernel<<<gemm_w, 256>>>(gx, w[i], nullptr, gt, M, HH, HH, 0);
            zero_kernel<<<zeroBlocksX, 256>>>(gx, xElems);
            spmm_kernel<<<spmmBlocks, 256>>>(rr, cc, vv, gt, gx, E);
            relu_norm_kernel<<<warpBlocks, 256>>>(gx, M, (i < 7) ? 1 : 0);
            mlp(gx, s);
        }
    };

    branch(a1r, a1c, a1v, gs1);
    branch(a2r, a2c, a2v, gs2);
    mul_kernel<<<(M + 255) / 256, 256>>>(gs1, gs2, out, M);
}

// round 3
// speedup vs baseline: 1.4649x; 1.4649x over previous
#include <cuda_runtime.h>
#include <cuda_bf16.h>
#include <math.h>
#include <cstdint>

#define NN 100000
#define HH 128
#define HD2 256

// ---------------- scratch (__device__ globals; no allocations allowed) -----
__device__ float g_x [(size_t)NN * HH];   // current features
__device__ float g_t [(size_t)NN * HH];   // x @ w
__device__ float g_h1[(size_t)NN * HD2];  // mlp hidden 1
__device__ float g_h2[(size_t)NN * HD2];  // mlp hidden 2
__device__ float g_s1[NN];
__device__ float g_s2[NN];

// transposed bf16-split weights, layout [n][k] (k contiguous) == mma "col"
#define WT_W(i)  ((size_t)(i) * 16384)
#define WT_M1    ((size_t)8 * 16384)
#define WT_M2    (WT_M1 + 32768)
#define WT_TOTAL (WT_M2 + 65536)
__device__ __nv_bfloat16 g_wth[WT_TOTAL];
__device__ __nv_bfloat16 g_wtl[WT_TOTAL];

// ---------------- helpers ----------------------------------------------------
__device__ __forceinline__ uint32_t smem_u32(const void* p) {
    uint32_t a;
    asm("{ .reg .u64 t; cvta.to.shared.u64 t, %1; cvt.u32.u64 %0, t; }" : "=r"(a) : "l"(p));
    return a;
}
__device__ __forceinline__ void ldmx4(uint32_t* r, uint32_t addr) {
    asm volatile("ldmatrix.sync.aligned.m8n8.x4.shared.b16 {%0,%1,%2,%3}, [%4];"
                 : "=r"(r[0]), "=r"(r[1]), "=r"(r[2]), "=r"(r[3]) : "r"(addr));
}
__device__ __forceinline__ void mma_bf16(float* c, const uint32_t* a, uint32_t b0, uint32_t b1) {
    asm volatile(
        "mma.sync.aligned.m16n8k16.row.col.f32.bf16.bf16.f32 "
        "{%0,%1,%2,%3}, {%4,%5,%6,%7}, {%8,%9}, {%0,%1,%2,%3};"
        : "+f"(c[0]), "+f"(c[1]), "+f"(c[2]), "+f"(c[3])
        : "r"(a[0]), "r"(a[1]), "r"(a[2]), "r"(a[3]), "r"(b0), "r"(b1));
}

// ---------------- small kernels ---------------------------------------------
__global__ void zero_kernel(float* __restrict__ p, size_t n) {
    size_t i = (size_t)blockIdx.x * blockDim.x + threadIdx.x;
    size_t stride = (size_t)gridDim.x * blockDim.x;
    for (; i < n; i += stride) p[i] = 0.0f;
}

// pre-transpose + bf16 hi/lo split: out[n*K+k] = W[k*Ncol+n]
__global__ void conv_w_kernel(const float* __restrict__ W, __nv_bfloat16* __restrict__ oh,
                              __nv_bfloat16* __restrict__ ol, int K, int Ncol) {
    int idx = blockIdx.x * blockDim.x + threadIdx.x;
    if (idx >= K * Ncol) return;
    int n = idx / K, k = idx - n * K;
    float v = W[(size_t)k * Ncol + n];
    __nv_bfloat16 h = __float2bfloat16(v);
    float r = v - __bfloat162float(h);
    oh[idx] = h;
    ol[idx] = __float2bfloat16(r);
}

// SpMM: warp per edge, float4 vector RED
__global__ void spmm_kernel(const int* __restrict__ rows, const int* __restrict__ cols,
                            const float* __restrict__ vals, const float* __restrict__ xin,
                            float* __restrict__ xout, int nE) {
    long long idx = (long long)blockIdx.x * blockDim.x + threadIdx.x;
    int e = (int)(idx >> 5);
    if (e >= nE) return;
    int lane = (int)(idx & 31);
    int r = __ldg(rows + e);
    int c = __ldg(cols + e);
    float v = __ldg(vals + e);
    float4 xv = *(const float4*)(xin + (size_t)c * HH + lane * 4);
    float4 p = make_float4(xv.x * v, xv.y * v, xv.z * v, xv.w * v);
    atomicAdd((float4*)(xout + (size_t)r * HH + lane * 4), p);
}

__global__ void relu_norm_kernel(float* __restrict__ x, int M, int do_norm) {
    long long idx = (long long)blockIdx.x * blockDim.x + threadIdx.x;
    int row = (int)(idx >> 5);
    if (row >= M) return;
    int lane = (int)(idx & 31);
    float4* p = (float4*)(x + (size_t)row * HH) + lane;
    float4 v = *p;
    v.x = fmaxf(v.x, 0.f); v.y = fmaxf(v.y, 0.f);
    v.z = fmaxf(v.z, 0.f); v.w = fmaxf(v.w, 0.f);
    if (do_norm) {
        float ss = v.x * v.x + v.y * v.y + v.z * v.z + v.w * v.w;
        #pragma unroll
        for (int o = 16; o; o >>= 1) ss += __shfl_xor_sync(0xffffffffu, ss, o);
        float inv = 1.0f / fmaxf(sqrtf(ss), 1e-12f);
        v.x *= inv; v.y *= inv; v.z *= inv; v.w *= inv;
    }
    *p = v;
}

__global__ void mlp3_kernel(const float* __restrict__ h, const float* __restrict__ m3,
                            const float* __restrict__ b3, float* __restrict__ s, int M) {
    long long idx = (long long)blockIdx.x * blockDim.x + threadIdx.x;
    int row = (int)(idx >> 5);
    if (row >= M) return;
    int lane = (int)(idx & 31);
    const float4* hp = (const float4*)(h + (size_t)row * HD2);
    const float4* mp = (const float4*)m3;
    float4 a = hp[lane],      ma = mp[lane];
    float4 b = hp[lane + 32], mb = mp[lane + 32];
    float d = a.x * ma.x + a.y * ma.y + a.z * ma.z + a.w * ma.w
            + b.x * mb.x + b.y * mb.y + b.z * mb.z + b.w * mb.w;
    #pragma unroll
    for (int o = 16; o; o >>= 1) d += __shfl_xor_sync(0xffffffffu, d, o);
    if (lane == 0) s[row] += d + b3[0];
}

__global__ void mul_kernel(const float* __restrict__ a, const float* __restrict__ b,
                           float* __restrict__ out, int M) {
    int i = blockIdx.x * blockDim.x + threadIdx.x;
    if (i < M) out[i] = a[i] * b[i];
}

// ---------------- mma.sync GEMM ----------------------------------------------
// C[M,Ncol] = A[M,K] @ W[K,Ncol]; W pre-split bf16 [Ncol][K] (col operand).
// 3-term split Ah*Bh + Ah*Bl + Al*Bh, fp32 accum in registers.
// BM=128, BN=128, BK=32; 8 warps (2x4), warp tile 64x32.
#define BK 32
#define LDP 40   // smem row stride in elems: 80B, 80/16=5 (odd) -> conflict-free ldmatrix

__global__ void __launch_bounds__(256, 1) tc_gemm_kernel(
    const float* __restrict__ A, const __nv_bfloat16* __restrict__ Bh,
    const __nv_bfloat16* __restrict__ Bl, const float* __restrict__ bias,
    float* __restrict__ C, int M, int K, int Ncol, int relu)
{
    __shared__ __align__(16) uint16_t As_h[128 * LDP];
    __shared__ __align__(16) uint16_t As_l[128 * LDP];
    __shared__ __align__(16) uint16_t Bs_h[128 * LDP];
    __shared__ __align__(16) uint16_t Bs_l[128 * LDP];

    const int tid = threadIdx.x;
    const int wid = tid >> 5, lane = tid & 31;
    const int mw = wid >> 2;          // 0..1 -> warp m offset mw*64
    const int nw = wid & 3;           // 0..3 -> warp n offset nw*32
    const int row0 = blockIdx.x * 128;
    const int n0 = blockIdx.y * 128;

    float acc[4][4][4] = {};

    const uint32_t sAh = smem_u32(As_h), sAl = smem_u32(As_l);
    const uint32_t sBh = smem_u32(Bs_h), sBl = smem_u32(Bs_l);

    // ldmatrix per-thread offsets (elements)
    const int a_row_sel = lane & 15;           // m within 16
    const int a_k_sel   = (lane >> 4) * 8;     // 0 or 8
    const int b_row_sel = (lane & 7) + ((lane >> 4) << 3);  // n within 16
    const int b_k_sel   = ((lane >> 3) & 1) * 8;            // 0 or 8

    const int nchunks = K / BK;
    for (int c = 0; c < nchunks; c++) {
        const int k0 = c * BK;
        // ---- stage A [128 x 32] fp32 -> hi/lo bf16 --------------------------
        #pragma unroll
        for (int i = 0; i < 4; i++) {
            int idx = tid + i * 256;            // 1024 float4 slots
            int r = idx >> 3, q = idx & 7;
            int grow = row0 + r;
            float4 v = make_float4(0.f, 0.f, 0.f, 0.f);
            if (grow < M) v = *(const float4*)(A + (size_t)grow * K + k0 + q * 4);
            __nv_bfloat16 h0 = __float2bfloat16(v.x), h1 = __float2bfloat16(v.y);
            __nv_bfloat16 h2 = __float2bfloat16(v.z), h3 = __float2bfloat16(v.w);
            __nv_bfloat16 l0 = __float2bfloat16(v.x - __bfloat162float(h0));
            __nv_bfloat16 l1 = __float2bfloat16(v.y - __bfloat162float(h1));
            __nv_bfloat16 l2 = __float2bfloat16(v.z - __bfloat162float(h2));
            __nv_bfloat16 l3 = __float2bfloat16(v.w - __bfloat162float(h3));
            uint2 hu, lu;
            hu.x = (uint32_t)__bfloat16_as_ushort(h0) | ((uint32_t)__bfloat16_as_ushort(h1) << 16);
            hu.y = (uint32_t)__bfloat16_as_ushort(h2) | ((uint32_t)__bfloat16_as_ushort(h3) << 16);
            lu.x = (uint32_t)__bfloat16_as_ushort(l0) | ((uint32_t)__bfloat16_as_ushort(l1) << 16);
            lu.y = (uint32_t)__bfloat16_as_ushort(l2) | ((uint32_t)__bfloat16_as_ushort(l3) << 16);
            *(uint2*)&As_h[r * LDP + q * 4] = hu;
            *(uint2*)&As_l[r * LDP + q * 4] = lu;
        }
        // ---- stage B [128 x 32] bf16 (pre-split) ----------------------------
        #pragma unroll
        for (int i = 0; i < 2; i++) {
            int idx = tid + i * 256;            // 512 uint4 slots
            int r = idx >> 2, q = idx & 3;
            size_t goff = (size_t)(n0 + r) * K + k0 + q * 8;
            *(uint4*)&Bs_h[r * LDP + q * 8] = *(const uint4*)(Bh + goff);
            *(uint4*)&Bs_l[r * LDP + q * 8] = *(const uint4*)(Bl + goff);
        }
        __syncthreads();

        // ---- compute: 2 k16 steps ------------------------------------------
        #pragma unroll
        for (int ks = 0; ks < 2; ks++) {
            const int koff = ks * 16;
            uint32_t ah[4][4], al[4][4];
            #pragma unroll
            for (int mi = 0; mi < 4; mi++) {
                uint32_t off = (uint32_t)((mw * 64 + mi * 16 + a_row_sel) * LDP
                                          + koff + a_k_sel) * 2;
                ldmx4(ah[mi], sAh + off);
                ldmx4(al[mi], sAl + off);
            }
            uint32_t bh[2][4], bl[2][4];
            #pragma unroll
            for (int p = 0; p < 2; p++) {
                uint32_t off = (uint32_t)((nw * 32 + p * 16 + b_row_sel) * LDP
                                          + koff + b_k_sel) * 2;
                ldmx4(bh[p], sBh + off);
                ldmx4(bl[p], sBl + off);
            }
            #pragma unroll
            for (int mi = 0; mi < 4; mi++) {
                #pragma unroll
                for (int ni = 0; ni < 4; ni++) {
                    uint32_t b0h = bh[ni >> 1][(ni & 1) * 2], b1h = bh[ni >> 1][(ni & 1) * 2 + 1];
                    uint32_t b0l = bl[ni >> 1][(ni & 1) * 2], b1l = bl[ni >> 1][(ni & 1) * 2 + 1];
                    mma_bf16(acc[mi][ni], ah[mi], b0h, b1h);
                    mma_bf16(acc[mi][ni], ah[mi], b0l, b1l);
                    mma_bf16(acc[mi][ni], al[mi], b0h, b1h);
                }
            }
        }
        __syncthreads();
    }

    // ---- epilogue: write C with bias/relu ----------------------------------
    const int mrow = row0 + mw * 64 + (lane >> 2);
    const int ncol = n0 + nw * 32 + (lane & 3) * 2;
    #pragma unroll
    for (int mi = 0; mi < 4; mi++) {
        int r_lo = mrow + mi * 16;
        int r_hi = r_lo + 8;
        #pragma unroll
        for (int ni = 0; ni < 4; ni++) {
            int col = ncol + ni * 8;
            float b0 = 0.f, b1 = 0.f;
            if (bias) { b0 = bias[col]; b1 = bias[col + 1]; }
            float v0 = acc[mi][ni][0] + b0, v1 = acc[mi][ni][1] + b1;
            float v2 = acc[mi][ni][2] + b0, v3 = acc[mi][ni][3] + b1;
            if (relu) {
                v0 = fmaxf(v0, 0.f); v1 = fmaxf(v1, 0.f);
                v2 = fmaxf(v2, 0.f); v3 = fmaxf(v3, 0.f);
            }
            if (r_lo < M) *(float2*)(C + (size_t)r_lo * Ncol + col) = make_float2(v0, v1);
            if (r_hi < M) *(float2*)(C + (size_t)r_hi * Ncol + col) = make_float2(v2, v3);
        }
    }
}

// ---------------- launch -----------------------------------------------------
extern "C" void kernel_launch(void* const* d_in, const int* in_sizes, int n_in,
                              void* d_out, int out_size) {
    const int*   a1r = (const int*)d_in[0];
    const int*   a1c = (const int*)d_in[1];
    const float* a1v = (const float*)d_in[2];
    const int*   a2r = (const int*)d_in[3];
    const int*   a2c = (const int*)d_in[4];
    const float* a2v = (const float*)d_in[5];
    const float* w1  = (const float*)d_in[6];
    const float* w[8];
    for (int i = 0; i < 8; i++) w[i] = (const float*)d_in[7 + i];
    const float* m1 = (const float*)d_in[15];
    const float* b1 = (const float*)d_in[16];
    const float* m2 = (const float*)d_in[17];
    const float* b2 = (const float*)d_in[18];
    const float* m3 = (const float*)d_in[19];
    const float* b3 = (const float*)d_in[20];
    float* out = (float*)d_out;

    const int E = in_sizes[0];
    const int M = in_sizes[6] / HH;

    float *gx, *gt, *gh1, *gh2, *gs1, *gs2;
    __nv_bfloat16 *wth, *wtl;
    cudaGetSymbolAddress((void**)&gx,  g_x);
    cudaGetSymbolAddress((void**)&gt,  g_t);
    cudaGetSymbolAddress((void**)&gh1, g_h1);
    cudaGetSymbolAddress((void**)&gh2, g_h2);
    cudaGetSymbolAddress((void**)&gs1, g_s1);
    cudaGetSymbolAddress((void**)&gs2, g_s2);
    cudaGetSymbolAddress((void**)&wth, g_wth);
    cudaGetSymbolAddress((void**)&wtl, g_wtl);

    // --- pre-split + transpose all weights to bf16 hi/lo --------------------
    for (int i = 0; i < 8; i++)
        conv_w_kernel<<<(16384 + 255) / 256, 256>>>(w[i], wth + WT_W(i), wtl + WT_W(i), HH, HH);
    conv_w_kernel<<<(32768 + 255) / 256, 256>>>(m1, wth + WT_M1, wtl + WT_M1, HH, HD2);
    conv_w_kernel<<<(65536 + 255) / 256, 256>>>(m2, wth + WT_M2, wtl + WT_M2, HD2, HD2);

    const int warpBlocks  = (int)(((long long)M * 32 + 255) / 256);
    const int spmmBlocks  = (int)(((long long)E * 32 + 255) / 256);
    const size_t xElems   = (size_t)M * HH;
    const int zeroBlocksX = (int)((xElems + 255) / 256);
    const int mtiles = (M + 127) / 128;

    dim3 g_w(mtiles, 1);   // [M,128] x [128,128]
    dim3 g_m1(mtiles, 2);  // [M,128] x [128,256]
    dim3 g_m2(mtiles, 2);  // [M,256] x [256,256]

    auto mlp = [&](const float* xin, float* s) {
        tc_gemm_kernel<<<g_m1, 256>>>(xin, wth + WT_M1, wtl + WT_M1, b1, gh1, M, HH, HD2, 1);
        tc_gemm_kernel<<<g_m2, 256>>>(gh1, wth + WT_M2, wtl + WT_M2, b2, gh2, M, HD2, HD2, 1);
        mlp3_kernel<<<warpBlocks, 256>>>(gh2, m3, b3, s, M);
    };

    auto branch = [&](const int* rr, const int* cc, const float* vv, float* s) {
        zero_kernel<<<(M + 255) / 256, 256>>>(s, (size_t)M);
        zero_kernel<<<zeroBlocksX, 256>>>(gx, xElems);
        spmm_kernel<<<spmmBlocks, 256>>>(rr, cc, vv, w1, gx, E);
        relu_norm_kernel<<<warpBlocks, 256>>>(gx, M, 1);
        mlp(gx, s);
        for (int i = 0; i < 8; i++) {
            tc_gemm_kernel<<<g_w, 256>>>(gx, wth + WT_W(i), wtl + WT_W(i), nullptr, gt, M, HH, HH, 0);
            zero_kernel<<<zeroBlocksX, 256>>>(gx, xElems);
            spmm_kernel<<<spmmBlocks, 256>>>(rr, cc, vv, gt, gx, E);
            relu_norm_kernel<<<warpBlocks, 256>>>(gx, M, (i < 7) ? 1 : 0);
            mlp(gx, s);
        }
    };

    branch(a1r, a1c, a1v, gs1);
    branch(a2r, a2c, a2v, gs2);
    mul_kernel<<<(M + 255) / 256, 256>>>(gs1, gs2, out, M);
}

// round 5
// speedup vs baseline: 2.0774x; 1.4181x over previous
#include <cuda_runtime.h>
#include <cuda_bf16.h>
#include <math.h>
#include <cstdint>

#define NN 100000
#define EE 1600000
#define HH 128
#define HD2 256

// ---------------- scratch (__device__ globals; no allocations allowed) -----
__device__ float g_xbuf[2][(size_t)NN * HH];  // ping-pong features
__device__ float g_t  [(size_t)NN * HH];      // x @ w
__device__ float g_h1 [(size_t)NN * HD2];     // mlp hidden 1
__device__ float g_s  [2][NN];                // scores per branch
// CSR (reused across the two branches; branches run serially)
__device__ int   g_rp  [NN + 1];
__device__ int   g_cnt [NN];
__device__ int   g_cols[EE];
__device__ float g_vals[EE];

// transposed bf16-split weights, layout [n][k] (k contiguous) == mma "col"
#define WT_W(i)  ((size_t)(i) * 16384)
#define WT_M1    ((size_t)8 * 16384)
#define WT_M2    (WT_M1 + 32768)
#define WT_TOTAL (WT_M2 + 65536)
__device__ __nv_bfloat16 g_wth[WT_TOTAL];
__device__ __nv_bfloat16 g_wtl[WT_TOTAL];

// ---------------- helpers ----------------------------------------------------
__device__ __forceinline__ uint32_t smem_u32(const void* p) {
    uint32_t a;
    asm("{ .reg .u64 t; cvta.to.shared.u64 t, %1; cvt.u32.u64 %0, t; }" : "=r"(a) : "l"(p));
    return a;
}
__device__ __forceinline__ void ldmx4(uint32_t* r, uint32_t addr) {
    asm volatile("ldmatrix.sync.aligned.m8n8.x4.shared.b16 {%0,%1,%2,%3}, [%4];"
                 : "=r"(r[0]), "=r"(r[1]), "=r"(r[2]), "=r"(r[3]) : "r"(addr));
}
__device__ __forceinline__ void mma_bf16(float* c, const uint32_t* a, uint32_t b0, uint32_t b1) {
    asm volatile(
        "mma.sync.aligned.m16n8k16.row.col.f32.bf16.bf16.f32 "
        "{%0,%1,%2,%3}, {%4,%5,%6,%7}, {%8,%9}, {%0,%1,%2,%3};"
        : "+f"(c[0]), "+f"(c[1]), "+f"(c[2]), "+f"(c[3])
        : "r"(a[0]), "r"(a[1]), "r"(a[2]), "r"(a[3]), "r"(b0), "r"(b1));
}

// ---------------- preprocessing kernels --------------------------------------
__global__ void conv_w_kernel(const float* __restrict__ W, __nv_bfloat16* __restrict__ oh,
                              __nv_bfloat16* __restrict__ ol, int K, int Ncol) {
    int idx = blockIdx.x * blockDim.x + threadIdx.x;
    if (idx >= K * Ncol) return;
    int n = idx / K, k = idx - n * K;
    float v = W[(size_t)k * Ncol + n];
    __nv_bfloat16 h = __float2bfloat16(v);
    float r = v - __bfloat162float(h);
    oh[idx] = h;
    ol[idx] = __float2bfloat16(r);
}

__global__ void init_score_kernel(float* __restrict__ s, const float* __restrict__ b3, int M) {
    int i = blockIdx.x * blockDim.x + threadIdx.x;
    if (i < M) s[i] = 9.0f * b3[0];
}

__global__ void zero_int_kernel(int* __restrict__ p, int n) {
    int i = blockIdx.x * blockDim.x + threadIdx.x;
    if (i < n) p[i] = 0;
}

__global__ void hist_kernel(const int* __restrict__ rows, int* __restrict__ cnt, int nE) {
    int e = blockIdx.x * blockDim.x + threadIdx.x;
    if (e < nE) atomicAdd(&cnt[rows[e]], 1);
}

// single-block exclusive scan: rp[0]=0, rp[i+1]=sum(cnt[0..i])
__global__ void scan_kernel(const int* __restrict__ cnt, int* __restrict__ rp, int n) {
    __shared__ int sdata[1024];
    __shared__ int carry;
    int tid = threadIdx.x;
    if (tid == 0) { carry = 0; rp[0] = 0; }
    __syncthreads();
    for (int base = 0; base < n; base += 1024) {
        int i = base + tid;
        int v = (i < n) ? cnt[i] : 0;
        sdata[tid] = v;
        __syncthreads();
        #pragma unroll
        for (int o = 1; o < 1024; o <<= 1) {
            int t = sdata[tid];
            if (tid >= o) t += sdata[tid - o];
            __syncthreads();
            sdata[tid] = t;
            __syncthreads();
        }
        if (i < n) rp[i + 1] = carry + sdata[tid];
        __syncthreads();
        if (tid == 0) carry += sdata[1023];
        __syncthreads();
    }
}

__global__ void copy_cursor_kernel(const int* __restrict__ rp, int* __restrict__ cur, int n) {
    int i = blockIdx.x * blockDim.x + threadIdx.x;
    if (i < n) cur[i] = rp[i];
}

__global__ void scatter_kernel(const int* __restrict__ rows, const int* __restrict__ cols,
                               const float* __restrict__ vals, int* __restrict__ cur,
                               int* __restrict__ cs, float* __restrict__ vs, int nE) {
    int e = blockIdx.x * blockDim.x + threadIdx.x;
    if (e >= nE) return;
    int pos = atomicAdd(&cur[rows[e]], 1);
    cs[pos] = cols[e];
    vs[pos] = vals[e];
}

// ---------------- CSR SpMM fused with relu (+ optional l2norm) ---------------
// warp per row; lane holds 4 contiguous cols
__global__ void spmm_csr_kernel(const int* __restrict__ rp, const int* __restrict__ cs,
                                const float* __restrict__ vs, const float* __restrict__ xin,
                                float* __restrict__ xout, int M, int do_norm) {
    long long idx = (long long)blockIdx.x * blockDim.x + threadIdx.x;
    int row = (int)(idx >> 5);
    if (row >= M) return;
    int lane = (int)(idx & 31);
    int s = __ldg(rp + row), e = __ldg(rp + row + 1);
    float ax = 0.f, ay = 0.f, az = 0.f, aw = 0.f;
    for (int j = s; j < e; j++) {
        int c = __ldg(cs + j);
        float v = __ldg(vs + j);
        float4 xv = *(const float4*)(xin + (size_t)c * HH + lane * 4);
        ax += v * xv.x; ay += v * xv.y; az += v * xv.z; aw += v * xv.w;
    }
    ax = fmaxf(ax, 0.f); ay = fmaxf(ay, 0.f);
    az = fmaxf(az, 0.f); aw = fmaxf(aw, 0.f);
    if (do_norm) {
        float ss = ax * ax + ay * ay + az * az + aw * aw;
        #pragma unroll
        for (int o = 16; o; o >>= 1) ss += __shfl_xor_sync(0xffffffffu, ss, o);
        float inv = 1.0f / fmaxf(sqrtf(ss), 1e-12f);
        ax *= inv; ay *= inv; az *= inv; aw *= inv;
    }
    *((float4*)(xout + (size_t)row * HH) + lane) = make_float4(ax, ay, az, aw);
}

__global__ void mul_kernel(const float* __restrict__ a, const float* __restrict__ b,
                           float* __restrict__ out, int M) {
    int i = blockIdx.x * blockDim.x + threadIdx.x;
    if (i < M) out[i] = a[i] * b[i];
}

// ---------------- mma.sync GEMM ----------------------------------------------
// C[M,Ncol] = A[M,K] @ W[K,Ncol]; W pre-split bf16 [Ncol][K] (col operand).
// 3-term split Ah*Bh + Ah*Bl + Al*Bh, fp32 accum.
// BM=128, BN=128, BK=32; 8 warps (2x4), warp tile 64x32.
// If m3s != nullptr: fused scoring epilogue (bias+relu+dot(m3)+atomicAdd(sc)),
// C is not written.
#define BK 32
#define LDP 40   // smem row stride (elems): 80B, odd multiple of 16B -> conflict-free

__global__ void __launch_bounds__(256, 1) tc_gemm_kernel(
    const float* __restrict__ A, const __nv_bfloat16* __restrict__ Bh,
    const __nv_bfloat16* __restrict__ Bl, const float* __restrict__ bias,
    float* __restrict__ C, int M, int K, int Ncol, int relu,
    const float* __restrict__ m3s, float* __restrict__ sc)
{
    __shared__ __align__(16) uint16_t As_h[128 * LDP];
    __shared__ __align__(16) uint16_t As_l[128 * LDP];
    __shared__ __align__(16) uint16_t Bs_h[128 * LDP];
    __shared__ __align__(16) uint16_t Bs_l[128 * LDP];

    const int tid = threadIdx.x;
    const int wid = tid >> 5, lane = tid & 31;
    const int mw = wid >> 2;
    const int nw = wid & 3;
    const int row0 = blockIdx.x * 128;
    const int n0 = blockIdx.y * 128;

    float acc[4][4][4] = {};

    const uint32_t sAh = smem_u32(As_h), sAl = smem_u32(As_l);
    const uint32_t sBh = smem_u32(Bs_h), sBl = smem_u32(Bs_l);

    const int a_row_sel = lane & 15;
    const int a_k_sel   = (lane >> 4) * 8;
    const int b_row_sel = (lane & 7) + ((lane >> 4) << 3);
    const int b_k_sel   = ((lane >> 3) & 1) * 8;

    const int nchunks = K / BK;
    for (int c = 0; c < nchunks; c++) {
        const int k0 = c * BK;
        #pragma unroll
        for (int i = 0; i < 4; i++) {
            int idx = tid + i * 256;
            int r = idx >> 3, q = idx & 7;
            int grow = row0 + r;
            float4 v = make_float4(0.f, 0.f, 0.f, 0.f);
            if (grow < M) v = *(const float4*)(A + (size_t)grow * K + k0 + q * 4);
            __nv_bfloat16 h0 = __float2bfloat16(v.x), h1 = __float2bfloat16(v.y);
            __nv_bfloat16 h2 = __float2bfloat16(v.z), h3 = __float2bfloat16(v.w);
            __nv_bfloat16 l0 = __float2bfloat16(v.x - __bfloat162float(h0));
            __nv_bfloat16 l1 = __float2bfloat16(v.y - __bfloat162float(h1));
            __nv_bfloat16 l2 = __float2bfloat16(v.z - __bfloat162float(h2));
            __nv_bfloat16 l3 = __float2bfloat16(v.w - __bfloat162float(h3));
            uint2 hu, lu;
            hu.x = (uint32_t)__bfloat16_as_ushort(h0) | ((uint32_t)__bfloat16_as_ushort(h1) << 16);
            hu.y = (uint32_t)__bfloat16_as_ushort(h2) | ((uint32_t)__bfloat16_as_ushort(h3) << 16);
            lu.x = (uint32_t)__bfloat16_as_ushort(l0) | ((uint32_t)__bfloat16_as_ushort(l1) << 16);
            lu.y = (uint32_t)__bfloat16_as_ushort(l2) | ((uint32_t)__bfloat16_as_ushort(l3) << 16);
            *(uint2*)&As_h[r * LDP + q * 4] = hu;
            *(uint2*)&As_l[r * LDP + q * 4] = lu;
        }
        #pragma unroll
        for (int i = 0; i < 2; i++) {
            int idx = tid + i * 256;
            int r = idx >> 2, q = idx & 3;
            size_t goff = (size_t)(n0 + r) * K + k0 + q * 8;
            *(uint4*)&Bs_h[r * LDP + q * 8] = *(const uint4*)(Bh + goff);
            *(uint4*)&Bs_l[r * LDP + q * 8] = *(const uint4*)(Bl + goff);
        }
        __syncthreads();

        #pragma unroll
        for (int ks = 0; ks < 2; ks++) {
            const int koff = ks * 16;
            uint32_t ah[4][4], al[4][4];
            #pragma unroll
            for (int mi = 0; mi < 4; mi++) {
                uint32_t off = (uint32_t)((mw * 64 + mi * 16 + a_row_sel) * LDP
                                          + koff + a_k_sel) * 2;
                ldmx4(ah[mi], sAh + off);
                ldmx4(al[mi], sAl + off);
            }
            uint32_t bh[2][4], bl[2][4];
            #pragma unroll
            for (int p = 0; p < 2; p++) {
                uint32_t off = (uint32_t)((nw * 32 + p * 16 + b_row_sel) * LDP
                                          + koff + b_k_sel) * 2;
                ldmx4(bh[p], sBh + off);
                ldmx4(bl[p], sBl + off);
            }
            #pragma unroll
            for (int mi = 0; mi < 4; mi++) {
                #pragma unroll
                for (int ni = 0; ni < 4; ni++) {
                    uint32_t b0h = bh[ni >> 1][(ni & 1) * 2], b1h = bh[ni >> 1][(ni & 1) * 2 + 1];
                    uint32_t b0l = bl[ni >> 1][(ni & 1) * 2], b1l = bl[ni >> 1][(ni & 1) * 2 + 1];
                    mma_bf16(acc[mi][ni], ah[mi], b0h, b1h);
                    mma_bf16(acc[mi][ni], ah[mi], b0l, b1l);
                    mma_bf16(acc[mi][ni], al[mi], b0h, b1h);
                }
            }
        }
        __syncthreads();
    }

    const int mrow = row0 + mw * 64 + (lane >> 2);
    const int ncol = n0 + nw * 32 + (lane & 3) * 2;

    if (m3s) {
        // fused scoring: sc[row] += sum_col relu(acc + bias[col]) * m3[col]
        #pragma unroll
        for (int mi = 0; mi < 4; mi++) {
            int r_lo = mrow + mi * 16;
            int r_hi = r_lo + 8;
            float plo = 0.f, phi = 0.f;
            #pragma unroll
            for (int ni = 0; ni < 4; ni++) {
                int col = ncol + ni * 8;
                float m30 = __ldg(m3s + col), m31 = __ldg(m3s + col + 1);
                float b0 = bias ? __ldg(bias + col) : 0.f;
                float b1 = bias ? __ldg(bias + col + 1) : 0.f;
                plo += fmaxf(acc[mi][ni][0] + b0, 0.f) * m30
                     + fmaxf(acc[mi][ni][1] + b1, 0.f) * m31;
                phi += fmaxf(acc[mi][ni][2] + b0, 0.f) * m30
                     + fmaxf(acc[mi][ni][3] + b1, 0.f) * m31;
            }
            plo += __shfl_xor_sync(0xffffffffu, plo, 1);
            plo += __shfl_xor_sync(0xffffffffu, plo, 2);
            phi += __shfl_xor_sync(0xffffffffu, phi, 1);
            phi += __shfl_xor_sync(0xffffffffu, phi, 2);
            if ((lane & 3) == 0) {
                if (r_lo < M) atomicAdd(sc + r_lo, plo);
                if (r_hi < M) atomicAdd(sc + r_hi, phi);
            }
        }
        return;
    }

    #pragma unroll
    for (int mi = 0; mi < 4; mi++) {
        int r_lo = mrow + mi * 16;
        int r_hi = r_lo + 8;
        #pragma unroll
        for (int ni = 0; ni < 4; ni++) {
            int col = ncol + ni * 8;
            float b0 = 0.f, b1 = 0.f;
            if (bias) { b0 = bias[col]; b1 = bias[col + 1]; }
            float v0 = acc[mi][ni][0] + b0, v1 = acc[mi][ni][1] + b1;
            float v2 = acc[mi][ni][2] + b0, v3 = acc[mi][ni][3] + b1;
            if (relu) {
                v0 = fmaxf(v0, 0.f); v1 = fmaxf(v1, 0.f);
                v2 = fmaxf(v2, 0.f); v3 = fmaxf(v3, 0.f);
            }
            if (r_lo < M) *(float2*)(C + (size_t)r_lo * Ncol + col) = make_float2(v0, v1);
            if (r_hi < M) *(float2*)(C + (size_t)r_hi * Ncol + col) = make_float2(v2, v3);
        }
    }
}

// ---------------- launch -----------------------------------------------------
extern "C" void kernel_launch(void* const* d_in, const int* in_sizes, int n_in,
                              void* d_out, int out_size) {
    const int*   adjr[2] = {(const int*)d_in[0], (const int*)d_in[3]};
    const int*   adjc[2] = {(const int*)d_in[1], (const int*)d_in[4]};
    const float* adjv[2] = {(const float*)d_in[2], (const float*)d_in[5]};
    const float* w1  = (const float*)d_in[6];
    const float* w[8];
    for (int i = 0; i < 8; i++) w[i] = (const float*)d_in[7 + i];
    const float* m1 = (const float*)d_in[15];
    const float* b1 = (const float*)d_in[16];
    const float* m2 = (const float*)d_in[17];
    const float* b2 = (const float*)d_in[18];
    const float* m3 = (const float*)d_in[19];
    const float* b3 = (const float*)d_in[20];
    float* out = (float*)d_out;

    const int E = in_sizes[0];
    const int M = in_sizes[6] / HH;

    float (*xbuf)[(size_t)NN * HH];
    float *gt, *gh1;
    float (*gs)[NN];
    int *rp, *cnt, *csc;
    float *csv;
    __nv_bfloat16 *wth, *wtl;
    cudaGetSymbolAddress((void**)&xbuf, g_xbuf);
    cudaGetSymbolAddress((void**)&gt,   g_t);
    cudaGetSymbolAddress((void**)&gh1,  g_h1);
    cudaGetSymbolAddress((void**)&gs,   g_s);
    cudaGetSymbolAddress((void**)&rp,   g_rp);
    cudaGetSymbolAddress((void**)&cnt,  g_cnt);
    cudaGetSymbolAddress((void**)&csc,  g_cols);
    cudaGetSymbolAddress((void**)&csv,  g_vals);
    cudaGetSymbolAddress((void**)&wth,  g_wth);
    cudaGetSymbolAddress((void**)&wtl,  g_wtl);

    // --- weights prep --------------------------------------------------------
    for (int i = 0; i < 8; i++)
        conv_w_kernel<<<64, 256>>>(w[i], wth + WT_W(i), wtl + WT_W(i), HH, HH);
    conv_w_kernel<<<128, 256>>>(m1, wth + WT_M1, wtl + WT_M1, HH, HD2);
    conv_w_kernel<<<256, 256>>>(m2, wth + WT_M2, wtl + WT_M2, HD2, HD2);

    const int warpBlocks = (int)(((long long)M * 32 + 255) / 256);
    const int eBlocks = (E + 255) / 256;
    const int nBlocks = (M + 255) / 256;
    const int mtiles = (M + 127) / 128;
    dim3 g_w(mtiles, 1);
    dim3 g_m(mtiles, 2);

    for (int b = 0; b < 2; b++) {
        // score init + CSR build (CSR buffers reused; branches are serial)
        init_score_kernel<<<nBlocks, 256>>>(gs[b], b3, M);
        zero_int_kernel<<<nBlocks, 256>>>(cnt, M);
        hist_kernel<<<eBlocks, 256>>>(adjr[b], cnt, E);
        scan_kernel<<<1, 1024>>>(cnt, rp, M);
        copy_cursor_kernel<<<nBlocks, 256>>>(rp, cnt, M);
        scatter_kernel<<<eBlocks, 256>>>(adjr[b], adjc[b], adjv[b], cnt, csc, csv, E);

        // layer 0: x = l2norm(relu(A @ w1))
        spmm_csr_kernel<<<warpBlocks, 256>>>(rp, csc, csv, w1, xbuf[0], M, 1);

        for (int L = 0; L <= 8; L++) {
            float* xc = xbuf[L & 1];
            // MLP scoring of layer L (fused: m2-GEMM epilogue does relu+dot(m3)+atomic)
            tc_gemm_kernel<<<g_m, 256>>>(xc, wth + WT_M1, wtl + WT_M1, b1, gh1,
                                         M, HH, HD2, 1, nullptr, nullptr);
            tc_gemm_kernel<<<g_m, 256>>>(gh1, wth + WT_M2, wtl + WT_M2, b2, nullptr,
                                         M, HD2, HD2, 1, m3, gs[b]);
            // main chain: layer L+1
            if (L < 8) {
                tc_gemm_kernel<<<g_w, 256>>>(xc, wth + WT_W(L), wtl + WT_W(L), nullptr,
                                             gt, M, HH, HH, 0, nullptr, nullptr);
                spmm_csr_kernel<<<warpBlocks, 256>>>(rp, csc, csv, gt,
                                                     xbuf[(L + 1) & 1], M,
                                                     (L + 1 < 8) ? 1 : 0);
            }
        }
    }

    mul_kernel<<<nBlocks, 256>>>(gs[0], gs[1], out, M);
}

// round 6
// speedup vs baseline: 2.4810x; 1.1943x over previous
#include <cuda_runtime.h>
#include <cuda_bf16.h>
#include <math.h>
#include <cstdint>

#define NN 100000
#define EE 1600000
#define HH 128
#define HD2 256

// ---------------- scratch (__device__ globals) -------------------------------
__device__ __nv_bfloat16 g_xh [(size_t)NN * HH];   // x hi
__device__ __nv_bfloat16 g_xl [(size_t)NN * HH];   // x lo
__device__ float         g_t  [(size_t)NN * HH];   // x @ w (fp32, spmm input)
__device__ __nv_bfloat16 g_h1h[(size_t)NN * HD2];  // mlp hidden hi
__device__ __nv_bfloat16 g_h1l[(size_t)NN * HD2];  // mlp hidden lo
__device__ float g_s[2][NN];
__device__ int   g_rp  [NN + 1];
__device__ int   g_cnt [NN];
__device__ int   g_cols[EE];
__device__ float g_vals[EE];

// transposed bf16-split weights, layout [n][k] (k contiguous) == mma "col"
#define WT_W(i)  ((size_t)(i) * 16384)
#define WT_M1    ((size_t)8 * 16384)
#define WT_M2    (WT_M1 + 32768)
#define WT_TOTAL (WT_M2 + 65536)
__device__ __nv_bfloat16 g_wth[WT_TOTAL];
__device__ __nv_bfloat16 g_wtl[WT_TOTAL];

// ---------------- helpers ----------------------------------------------------
__device__ __forceinline__ uint32_t smem_u32(const void* p) {
    uint32_t a;
    asm("{ .reg .u64 t; cvta.to.shared.u64 t, %1; cvt.u32.u64 %0, t; }" : "=r"(a) : "l"(p));
    return a;
}
__device__ __forceinline__ void ldmx4(uint32_t* r, uint32_t addr) {
    asm volatile("ldmatrix.sync.aligned.m8n8.x4.shared.b16 {%0,%1,%2,%3}, [%4];"
                 : "=r"(r[0]), "=r"(r[1]), "=r"(r[2]), "=r"(r[3]) : "r"(addr));
}
__device__ __forceinline__ void mma_bf16(float* c, const uint32_t* a, uint32_t b0, uint32_t b1) {
    asm volatile(
        "mma.sync.aligned.m16n8k16.row.col.f32.bf16.bf16.f32 "
        "{%0,%1,%2,%3}, {%4,%5,%6,%7}, {%8,%9}, {%0,%1,%2,%3};"
        : "+f"(c[0]), "+f"(c[1]), "+f"(c[2]), "+f"(c[3])
        : "r"(a[0]), "r"(a[1]), "r"(a[2]), "r"(a[3]), "r"(b0), "r"(b1));
}
__device__ __forceinline__ void cpa16(uint32_t dst, const void* src, int nbytes) {
    asm volatile("cp.async.cg.shared.global [%0], [%1], 16, %2;"
                 :: "r"(dst), "l"(src), "r"(nbytes) : "memory");
}
__device__ __forceinline__ void pack_hl(float a, float b, uint32_t& hu, uint32_t& lu) {
    __nv_bfloat16 ha = __float2bfloat16(a), hb = __float2bfloat16(b);
    __nv_bfloat16 la = __float2bfloat16(a - __bfloat162float(ha));
    __nv_bfloat16 lb = __float2bfloat16(b - __bfloat162float(hb));
    hu = (uint32_t)__bfloat16_as_ushort(ha) | ((uint32_t)__bfloat16_as_ushort(hb) << 16);
    lu = (uint32_t)__bfloat16_as_ushort(la) | ((uint32_t)__bfloat16_as_ushort(lb) << 16);
}

// ---------------- fused preprocessing ----------------------------------------
struct ConvSrcs { const float* p[10]; };

__global__ void conv_all_kernel(ConvSrcs srcs, __nv_bfloat16* __restrict__ oh,
                                __nv_bfloat16* __restrict__ ol, int* __restrict__ cnt) {
    int gid = blockIdx.x * blockDim.x + threadIdx.x;
    if (gid < (int)WT_TOTAL) {
        const float* W; int local, K, Ncol;
        if (gid < 131072)               { W = srcs.p[gid >> 14]; local = gid & 16383;            K = HH;  Ncol = HH;  }
        else if (gid < 131072 + 32768)  { W = srcs.p[8];         local = gid - 131072;           K = HH;  Ncol = HD2; }
        else                            { W = srcs.p[9];         local = gid - (131072 + 32768); K = HD2; Ncol = HD2; }
        int n = local / K, k = local - n * K;
        float v = W[(size_t)k * Ncol + n];
        __nv_bfloat16 h = __float2bfloat16(v);
        oh[gid] = h;
        ol[gid] = __float2bfloat16(v - __bfloat162float(h));
    } else {
        int j = gid - (int)WT_TOTAL;
        if (j < NN) cnt[j] = 0;
    }
}

__global__ void zero_int_kernel(int* __restrict__ p, int n) {
    int i = blockIdx.x * blockDim.x + threadIdx.x;
    if (i < n) p[i] = 0;
}

__global__ void hist_kernel(const int* __restrict__ rows, int* __restrict__ cnt, int nE) {
    int e = blockIdx.x * blockDim.x + threadIdx.x;
    if (e < nE) atomicAdd(&cnt[rows[e]], 1);
}

// single-block scan: rp[0]=0, rp[i+1]=incl(i), cur[i]=rp[i]
__global__ void scan_kernel(const int* __restrict__ cnt, int* __restrict__ rp,
                            int* __restrict__ cur, int n) {
    __shared__ int sdata[1024];
    __shared__ int carry;
    int tid = threadIdx.x;
    if (tid == 0) { carry = 0; rp[0] = 0; }
    __syncthreads();
    for (int base = 0; base < n; base += 1024) {
        int i = base + tid;
        int v = (i < n) ? cnt[i] : 0;
        sdata[tid] = v;
        __syncthreads();
        #pragma unroll
        for (int o = 1; o < 1024; o <<= 1) {
            int t = sdata[tid];
            if (tid >= o) t += sdata[tid - o];
            __syncthreads();
            sdata[tid] = t;
            __syncthreads();
        }
        if (i < n) {
            int incl = carry + sdata[tid];
            rp[i + 1] = incl;
            cur[i] = incl - v;
        }
        __syncthreads();
        if (tid == 0) carry += sdata[1023];
        __syncthreads();
    }
}

// scatter + score init (score = 9*b3 since mlp adds b3 nine times)
__global__ void scatter_kernel(const int* __restrict__ rows, const int* __restrict__ cols,
                               const float* __restrict__ vals, int* __restrict__ cur,
                               int* __restrict__ cs, float* __restrict__ vs, int nE,
                               float* __restrict__ s, const float* __restrict__ b3, int M) {
    int e = blockIdx.x * blockDim.x + threadIdx.x;
    if (e < M) s[e] = 9.0f * b3[0];
    if (e >= nE) return;
    int pos = atomicAdd(&cur[rows[e]], 1);
    cs[pos] = cols[e];
    vs[pos] = vals[e];
}

// ---------------- CSR SpMM fused relu(+norm), bf16 hi/lo split output --------
__global__ void spmm_csr_kernel(const int* __restrict__ rp, const int* __restrict__ cs,
                                const float* __restrict__ vs, const float* __restrict__ xin,
                                __nv_bfloat16* __restrict__ xh, __nv_bfloat16* __restrict__ xl,
                                int M, int do_norm) {
    long long idx = (long long)blockIdx.x * blockDim.x + threadIdx.x;
    int row = (int)(idx >> 5);
    if (row >= M) return;
    int lane = (int)(idx & 31);
    int s = __ldg(rp + row), e = __ldg(rp + row + 1);
    float ax = 0.f, ay = 0.f, az = 0.f, aw = 0.f;
    for (int j = s; j < e; j++) {
        int c = __ldg(cs + j);
        float v = __ldg(vs + j);
        float4 xv = *(const float4*)(xin + (size_t)c * HH + lane * 4);
        ax += v * xv.x; ay += v * xv.y; az += v * xv.z; aw += v * xv.w;
    }
    ax = fmaxf(ax, 0.f); ay = fmaxf(ay, 0.f);
    az = fmaxf(az, 0.f); aw = fmaxf(aw, 0.f);
    if (do_norm) {
        float ss = ax * ax + ay * ay + az * az + aw * aw;
        #pragma unroll
        for (int o = 16; o; o >>= 1) ss += __shfl_xor_sync(0xffffffffu, ss, o);
        float inv = 1.0f / fmaxf(sqrtf(ss), 1e-12f);
        ax *= inv; ay *= inv; az *= inv; aw *= inv;
    }
    uint2 hv, lv;
    pack_hl(ax, ay, hv.x, lv.x);
    pack_hl(az, aw, hv.y, lv.y);
    size_t off = (size_t)row * HH + lane * 4;
    *(uint2*)(xh + off) = hv;
    *(uint2*)(xl + off) = lv;
}

__global__ void mul_kernel(const float* __restrict__ a, const float* __restrict__ b,
                           float* __restrict__ out, int M) {
    int i = blockIdx.x * blockDim.x + threadIdx.x;
    if (i < M) out[i] = a[i] * b[i];
}

// ---------------- pipelined mma.sync GEMM -------------------------------------
// C = A @ W ; A pre-split bf16 (Ah,Al) [M][K]; W pre-split bf16 [Ncol][K].
// 3-term Markidis: AhBh + AhBl + AlBh, fp32 accum.
// BM=128,BN=128,BK=32; 8 warps (2x4); cp.async 2-stage pipeline.
// Epilogues: (a) m3s!=0: fused scoring -> atomicAdd(sc)
//            (b) Ch!=0:  relu + split bf16 hi/lo write (h1)
//            (c) else:   fp32 C write (+optional relu)
#define BK 32
#define LDP 40                      // row stride elems: 80B, odd*16B -> ldmatrix conflict-free
#define STG_ELEMS (128 * LDP)       // per array per stage
#define GEMM_SMEM (2 * 4 * STG_ELEMS * 2)  // 81920 B

__global__ void __launch_bounds__(256, 1) tc_gemm_kernel(
    const __nv_bfloat16* __restrict__ Ah, const __nv_bfloat16* __restrict__ Al,
    const __nv_bfloat16* __restrict__ Bh, const __nv_bfloat16* __restrict__ Bl,
    const float* __restrict__ bias, float* __restrict__ C,
    __nv_bfloat16* __restrict__ Ch, __nv_bfloat16* __restrict__ Cl,
    int M, int K, int Ncol, int relu,
    const float* __restrict__ m3s, float* __restrict__ sc)
{
    extern __shared__ __align__(16) uint16_t smem[];
    const int tid = threadIdx.x;
    const int wid = tid >> 5, lane = tid & 31;
    const int mw = wid >> 2, nw = wid & 3;
    const int row0 = blockIdx.x * 128;
    const int n0 = blockIdx.y * 128;

    float acc[4][4][4] = {};
    const uint32_t sbase = smem_u32(smem);
    auto abase = [&](int stage, int arr) {
        return sbase + (uint32_t)(((stage << 2) + arr) * STG_ELEMS * 2);
    };

    auto load_chunk = [&](int c, int stage) {
        const int k0 = c * BK;
        #pragma unroll
        for (int i = 0; i < 2; i++) {
            int idx = tid + i * 256;
            int r = idx >> 2, q = idx & 3;
            uint32_t doff = (uint32_t)(r * LDP + q * 8) * 2;
            int grow = row0 + r;
            int pa = (grow < M) ? 16 : 0;
            int ga = grow < M ? grow : (M - 1);
            cpa16(abase(stage, 0) + doff, Ah + (size_t)ga * K + k0 + q * 8, pa);
            cpa16(abase(stage, 1) + doff, Al + (size_t)ga * K + k0 + q * 8, pa);
            cpa16(abase(stage, 2) + doff, Bh + (size_t)(n0 + r) * K + k0 + q * 8, 16);
            cpa16(abase(stage, 3) + doff, Bl + (size_t)(n0 + r) * K + k0 + q * 8, 16);
        }
    };

    const int a_row_sel = lane & 15;
    const int a_k_sel   = (lane >> 4) * 8;
    const int b_row_sel = (lane & 7) + ((lane >> 4) << 3);
    const int b_k_sel   = ((lane >> 3) & 1) * 8;

    const int nchunks = K / BK;
    load_chunk(0, 0);
    asm volatile("cp.async.commit_group;" ::: "memory");

    for (int c = 0; c < nchunks; c++) {
        if (c + 1 < nchunks) load_chunk(c + 1, (c + 1) & 1);
        asm volatile("cp.async.commit_group;" ::: "memory");
        asm volatile("cp.async.wait_group 1;" ::: "memory");
        __syncthreads();
        const int st = c & 1;
        const uint32_t sAh = abase(st, 0), sAl = abase(st, 1);
        const uint32_t sBh = abase(st, 2), sBl = abase(st, 3);
        #pragma unroll
        for (int ks = 0; ks < 2; ks++) {
            const int koff = ks * 16;
            uint32_t ah[4][4], al[4][4];
            #pragma unroll
            for (int mi = 0; mi < 4; mi++) {
                uint32_t off = (uint32_t)((mw * 64 + mi * 16 + a_row_sel) * LDP
                                          + koff + a_k_sel) * 2;
                ldmx4(ah[mi], sAh + off);
                ldmx4(al[mi], sAl + off);
            }
            uint32_t bh[2][4], bl[2][4];
            #pragma unroll
            for (int p = 0; p < 2; p++) {
                uint32_t off = (uint32_t)((nw * 32 + p * 16 + b_row_sel) * LDP
                                          + koff + b_k_sel) * 2;
                ldmx4(bh[p], sBh + off);
                ldmx4(bl[p], sBl + off);
            }
            #pragma unroll
            for (int mi = 0; mi < 4; mi++) {
                #pragma unroll
                for (int ni = 0; ni < 4; ni++) {
                    uint32_t b0h = bh[ni >> 1][(ni & 1) * 2], b1h = bh[ni >> 1][(ni & 1) * 2 + 1];
                    uint32_t b0l = bl[ni >> 1][(ni & 1) * 2], b1l = bl[ni >> 1][(ni & 1) * 2 + 1];
                    mma_bf16(acc[mi][ni], ah[mi], b0h, b1h);
                    mma_bf16(acc[mi][ni], ah[mi], b0l, b1l);
                    mma_bf16(acc[mi][ni], al[mi], b0h, b1h);
                }
            }
        }
        __syncthreads();
    }

    const int mrow = row0 + mw * 64 + (lane >> 2);
    const int ncol = n0 + nw * 32 + (lane & 3) * 2;

    if (m3s) {  // fused scoring
        #pragma unroll
        for (int mi = 0; mi < 4; mi++) {
            int r_lo = mrow + mi * 16;
            int r_hi = r_lo + 8;
            float plo = 0.f, phi = 0.f;
            #pragma unroll
            for (int ni = 0; ni < 4; ni++) {
                int col = ncol + ni * 8;
                float m30 = __ldg(m3s + col), m31 = __ldg(m3s + col + 1);
                float b0 = __ldg(bias + col), b1 = __ldg(bias + col + 1);
                plo += fmaxf(acc[mi][ni][0] + b0, 0.f) * m30
                     + fmaxf(acc[mi][ni][1] + b1, 0.f) * m31;
                phi += fmaxf(acc[mi][ni][2] + b0, 0.f) * m30
                     + fmaxf(acc[mi][ni][3] + b1, 0.f) * m31;
            }
            plo += __shfl_xor_sync(0xffffffffu, plo, 1);
            plo += __shfl_xor_sync(0xffffffffu, plo, 2);
            phi += __shfl_xor_sync(0xffffffffu, phi, 1);
            phi += __shfl_xor_sync(0xffffffffu, phi, 2);
            if ((lane & 3) == 0) {
                if (r_lo < M) atomicAdd(sc + r_lo, plo);
                if (r_hi < M) atomicAdd(sc + r_hi, phi);
            }
        }
        return;
    }

    if (Ch) {  // relu + bf16 hi/lo split write (h1 producer)
        #pragma unroll
        for (int mi = 0; mi < 4; mi++) {
            int r_lo = mrow + mi * 16;
            int r_hi = r_lo + 8;
            #pragma unroll
            for (int ni = 0; ni < 4; ni++) {
                int col = ncol + ni * 8;
                float b0 = bias ? __ldg(bias + col) : 0.f;
                float b1 = bias ? __ldg(bias + col + 1) : 0.f;
                float v0 = fmaxf(acc[mi][ni][0] + b0, 0.f);
                float v1 = fmaxf(acc[mi][ni][1] + b1, 0.f);
                float v2 = fmaxf(acc[mi][ni][2] + b0, 0.f);
                float v3 = fmaxf(acc[mi][ni][3] + b1, 0.f);
                uint32_t hu, lu;
                if (r_lo < M) {
                    pack_hl(v0, v1, hu, lu);
                    *(uint32_t*)(Ch + (size_t)r_lo * Ncol + col) = hu;
                    *(uint32_t*)(Cl + (size_t)r_lo * Ncol + col) = lu;
                }
                if (r_hi < M) {
                    pack_hl(v2, v3, hu, lu);
                    *(uint32_t*)(Ch + (size_t)r_hi * Ncol + col) = hu;
                    *(uint32_t*)(Cl + (size_t)r_hi * Ncol + col) = lu;
                }
            }
        }
        return;
    }

    #pragma unroll
    for (int mi = 0; mi < 4; mi++) {
        int r_lo = mrow + mi * 16;
        int r_hi = r_lo + 8;
        #pragma unroll
        for (int ni = 0; ni < 4; ni++) {
            int col = ncol + ni * 8;
            float v0 = acc[mi][ni][0], v1 = acc[mi][ni][1];
            float v2 = acc[mi][ni][2], v3 = acc[mi][ni][3];
            if (relu) {
                v0 = fmaxf(v0, 0.f); v1 = fmaxf(v1, 0.f);
                v2 = fmaxf(v2, 0.f); v3 = fmaxf(v3, 0.f);
            }
            if (r_lo < M) *(float2*)(C + (size_t)r_lo * Ncol + col) = make_float2(v0, v1);
            if (r_hi < M) *(float2*)(C + (size_t)r_hi * Ncol + col) = make_float2(v2, v3);
        }
    }
}

// ---------------- launch -----------------------------------------------------
extern "C" void kernel_launch(void* const* d_in, const int* in_sizes, int n_in,
                              void* d_out, int out_size) {
    const int*   adjr[2] = {(const int*)d_in[0], (const int*)d_in[3]};
    const int*   adjc[2] = {(const int*)d_in[1], (const int*)d_in[4]};
    const float* adjv[2] = {(const float*)d_in[2], (const float*)d_in[5]};
    const float* w1 = (const float*)d_in[6];
    const float* m1 = (const float*)d_in[15];
    const float* b1 = (const float*)d_in[16];
    const float* m2 = (const float*)d_in[17];
    const float* b2 = (const float*)d_in[18];
    const float* m3 = (const float*)d_in[19];
    const float* b3 = (const float*)d_in[20];
    float* out = (float*)d_out;

    const int E = in_sizes[0];
    const int M = in_sizes[6] / HH;

    __nv_bfloat16 *xh, *xl, *h1h, *h1l, *wth, *wtl;
    float *gt, *csv;
    float (*gs)[NN];
    int *rp, *cnt, *csc;
    cudaGetSymbolAddress((void**)&xh,  g_xh);
    cudaGetSymbolAddress((void**)&xl,  g_xl);
    cudaGetSymbolAddress((void**)&gt,  g_t);
    cudaGetSymbolAddress((void**)&h1h, g_h1h);
    cudaGetSymbolAddress((void**)&h1l, g_h1l);
    cudaGetSymbolAddress((void**)&gs,  g_s);
    cudaGetSymbolAddress((void**)&rp,  g_rp);
    cudaGetSymbolAddress((void**)&cnt, g_cnt);
    cudaGetSymbolAddress((void**)&csc, g_cols);
    cudaGetSymbolAddress((void**)&csv, g_vals);
    cudaGetSymbolAddress((void**)&wth, g_wth);
    cudaGetSymbolAddress((void**)&wtl, g_wtl);

    cudaFuncSetAttribute(tc_gemm_kernel,
                         cudaFuncAttributeMaxDynamicSharedMemorySize, GEMM_SMEM);

    // launch #0: all weight conversions + cnt zeroing (one kernel)
    ConvSrcs cs;
    for (int i = 0; i < 8; i++) cs.p[i] = (const float*)d_in[7 + i];
    cs.p[8] = m1; cs.p[9] = m2;
    {
        int tot = (int)WT_TOTAL + NN;
        conv_all_kernel<<<(tot + 255) / 256, 256>>>(cs, wth, wtl, cnt);
    }

    const int warpBlocks = (int)(((long long)M * 32 + 255) / 256);
    const int eBlocks = (E + 255) / 256;
    const int nBlocks = (M + 255) / 256;
    const int mtiles = (M + 127) / 128;
    dim3 g_w(mtiles, 1);
    dim3 g_m(mtiles, 2);

    for (int b = 0; b < 2; b++) {
        if (b) zero_int_kernel<<<nBlocks, 256>>>(cnt, M);        // cnt reused
        hist_kernel<<<eBlocks, 256>>>(adjr[b], cnt, E);          // #1
        scan_kernel<<<1, 1024>>>(cnt, rp, cnt, M);               // #2 (rp + cursor)
        scatter_kernel<<<eBlocks, 256>>>(adjr[b], adjc[b], adjv[b], cnt, csc, csv,
                                         E, gs[b], b3, M);       // #3
        // layer 0: x = l2norm(relu(A @ w1)), split bf16
        spmm_csr_kernel<<<warpBlocks, 256>>>(rp, csc, csv, w1, xh, xl, M, 1);  // #4

        for (int L = 0; L <= 8; L++) {
            // MLP scoring (m1: split h1 producer; m2: fused scoring epilogue)
            tc_gemm_kernel<<<g_m, 256, GEMM_SMEM>>>(xh, xl, wth + WT_M1, wtl + WT_M1,
                                                    b1, nullptr, h1h, h1l,
                                                    M, HH, HD2, 1, nullptr, nullptr);  // #5
            tc_gemm_kernel<<<g_m, 256, GEMM_SMEM>>>(h1h, h1l, wth + WT_M2, wtl + WT_M2,
                                                    b2, nullptr, nullptr, nullptr,
                                                    M, HD2, HD2, 1, m3, gs[b]);
            if (L < 8) {
                tc_gemm_kernel<<<g_w, 256, GEMM_SMEM>>>(xh, xl, wth + WT_W(L), wtl + WT_W(L),
                                                        nullptr, gt, nullptr, nullptr,
                                                        M, HH, HH, 0, nullptr, nullptr);
                spmm_csr_kernel<<<warpBlocks, 256>>>(rp, csc, csv, gt, xh, xl, M,
                                                     (L + 1 < 8) ? 1 : 0);
            }
        }
    }

    mul_kernel<<<nBlocks, 256>>>(gs[0], gs[1], out, M);
}

// round 7
// speedup vs baseline: 2.4831x; 1.0009x over previous
#include <cuda_runtime.h>
#include <cuda_bf16.h>
#include <math.h>
#include <cstdint>

#define NN 100000
#define EE 1600000
#define HH 128
#define HD2 256

// ---------------- scratch (__device__ globals) -------------------------------
__device__ __nv_bfloat16 g_xh [(size_t)NN * HH];   // x hi
__device__ __nv_bfloat16 g_xl [(size_t)NN * HH];   // x lo
__device__ float         g_t  [(size_t)NN * HH];   // x @ w (fp32, spmm input)
__device__ __nv_bfloat16 g_h1h[(size_t)NN * HD2];  // mlp hidden hi
__device__ __nv_bfloat16 g_h1l[(size_t)NN * HD2];  // mlp hidden lo
__device__ float g_s[2][NN];
__device__ int   g_rp  [NN + 1];
__device__ int   g_cnt [NN];
__device__ int   g_cols[EE];
__device__ float g_vals[EE];

// transposed bf16-split weights, layout [n][k] (k contiguous) == mma "col"
#define WT_W(i)  ((size_t)(i) * 16384)
#define WT_M1    ((size_t)8 * 16384)
#define WT_M2    (WT_M1 + 32768)
#define WT_TOTAL (WT_M2 + 65536)
__device__ __nv_bfloat16 g_wth[WT_TOTAL];
__device__ __nv_bfloat16 g_wtl[WT_TOTAL];

// ---------------- helpers ----------------------------------------------------
__device__ __forceinline__ uint32_t smem_u32(const void* p) {
    uint32_t a;
    asm("{ .reg .u64 t; cvta.to.shared.u64 t, %1; cvt.u32.u64 %0, t; }" : "=r"(a) : "l"(p));
    return a;
}
__device__ __forceinline__ void ldmx4(uint32_t* r, uint32_t addr) {
    asm volatile("ldmatrix.sync.aligned.m8n8.x4.shared.b16 {%0,%1,%2,%3}, [%4];"
                 : "=r"(r[0]), "=r"(r[1]), "=r"(r[2]), "=r"(r[3]) : "r"(addr));
}
__device__ __forceinline__ void mma_bf16(float* c, const uint32_t* a, uint32_t b0, uint32_t b1) {
    asm volatile(
        "mma.sync.aligned.m16n8k16.row.col.f32.bf16.bf16.f32 "
        "{%0,%1,%2,%3}, {%4,%5,%6,%7}, {%8,%9}, {%0,%1,%2,%3};"
        : "+f"(c[0]), "+f"(c[1]), "+f"(c[2]), "+f"(c[3])
        : "r"(a[0]), "r"(a[1]), "r"(a[2]), "r"(a[3]), "r"(b0), "r"(b1));
}
__device__ __forceinline__ void cpa16(uint32_t dst, const void* src, int nbytes) {
    asm volatile("cp.async.cg.shared.global [%0], [%1], 16, %2;"
                 :: "r"(dst), "l"(src), "r"(nbytes) : "memory");
}
__device__ __forceinline__ void pack_hl(float a, float b, uint32_t& hu, uint32_t& lu) {
    __nv_bfloat16 ha = __float2bfloat16(a), hb = __float2bfloat16(b);
    __nv_bfloat16 la = __float2bfloat16(a - __bfloat162float(ha));
    __nv_bfloat16 lb = __float2bfloat16(b - __bfloat162float(hb));
    hu = (uint32_t)__bfloat16_as_ushort(ha) | ((uint32_t)__bfloat16_as_ushort(hb) << 16);
    lu = (uint32_t)__bfloat16_as_ushort(la) | ((uint32_t)__bfloat16_as_ushort(lb) << 16);
}

// ---------------- fused preprocessing ----------------------------------------
struct ConvSrcs { const float* p[10]; };

__global__ void conv_all_kernel(ConvSrcs srcs, __nv_bfloat16* __restrict__ oh,
                                __nv_bfloat16* __restrict__ ol, int* __restrict__ cnt) {
    int gid = blockIdx.x * blockDim.x + threadIdx.x;
    if (gid < (int)WT_TOTAL) {
        const float* W; int local, K, Ncol;
        if (gid < 131072)               { W = srcs.p[gid >> 14]; local = gid & 16383;            K = HH;  Ncol = HH;  }
        else if (gid < 131072 + 32768)  { W = srcs.p[8];         local = gid - 131072;           K = HH;  Ncol = HD2; }
        else                            { W = srcs.p[9];         local = gid - (131072 + 32768); K = HD2; Ncol = HD2; }
        int n = local / K, k = local - n * K;
        float v = W[(size_t)k * Ncol + n];
        __nv_bfloat16 h = __float2bfloat16(v);
        oh[gid] = h;
        ol[gid] = __float2bfloat16(v - __bfloat162float(h));
    } else {
        int j = gid - (int)WT_TOTAL;
        if (j < NN) cnt[j] = 0;
    }
}

__global__ void zero_int_kernel(int* __restrict__ p, int n) {
    int i = blockIdx.x * blockDim.x + threadIdx.x;
    if (i < n) p[i] = 0;
}

__global__ void hist_kernel(const int* __restrict__ rows, int* __restrict__ cnt, int nE) {
    int e = blockIdx.x * blockDim.x + threadIdx.x;
    if (e < nE) atomicAdd(&cnt[rows[e]], 1);
}

// single-block scan: rp[0]=0, rp[i+1]=incl(i), cur[i]=rp[i]
__global__ void scan_kernel(const int* __restrict__ cnt, int* __restrict__ rp,
                            int* __restrict__ cur, int n) {
    __shared__ int sdata[1024];
    __shared__ int carry;
    int tid = threadIdx.x;
    if (tid == 0) { carry = 0; rp[0] = 0; }
    __syncthreads();
    for (int base = 0; base < n; base += 1024) {
        int i = base + tid;
        int v = (i < n) ? cnt[i] : 0;
        sdata[tid] = v;
        __syncthreads();
        #pragma unroll
        for (int o = 1; o < 1024; o <<= 1) {
            int t = sdata[tid];
            if (tid >= o) t += sdata[tid - o];
            __syncthreads();
            sdata[tid] = t;
            __syncthreads();
        }
        if (i < n) {
            int incl = carry + sdata[tid];
            rp[i + 1] = incl;
            cur[i] = incl - v;
        }
        __syncthreads();
        if (tid == 0) carry += sdata[1023];
        __syncthreads();
    }
}

// scatter + score init (score = 9*b3 since mlp adds b3 nine times)
__global__ void scatter_kernel(const int* __restrict__ rows, const int* __restrict__ cols,
                               const float* __restrict__ vals, int* __restrict__ cur,
                               int* __restrict__ cs, float* __restrict__ vs, int nE,
                               float* __restrict__ s, const float* __restrict__ b3, int M) {
    int e = blockIdx.x * blockDim.x + threadIdx.x;
    if (e < M) s[e] = 9.0f * b3[0];
    if (e >= nE) return;
    int pos = atomicAdd(&cur[rows[e]], 1);
    cs[pos] = cols[e];
    vs[pos] = vals[e];
}

// ---------------- CSR SpMM fused relu(+norm), bf16 hi/lo split output --------
__global__ void spmm_csr_kernel(const int* __restrict__ rp, const int* __restrict__ cs,
                                const float* __restrict__ vs, const float* __restrict__ xin,
                                __nv_bfloat16* __restrict__ xh, __nv_bfloat16* __restrict__ xl,
                                int M, int do_norm) {
    long long idx = (long long)blockIdx.x * blockDim.x + threadIdx.x;
    int row = (int)(idx >> 5);
    if (row >= M) return;
    int lane = (int)(idx & 31);
    int s = __ldg(rp + row), e = __ldg(rp + row + 1);
    float ax = 0.f, ay = 0.f, az = 0.f, aw = 0.f;
    for (int j = s; j < e; j++) {
        int c = __ldg(cs + j);
        float v = __ldg(vs + j);
        float4 xv = *(const float4*)(xin + (size_t)c * HH + lane * 4);
        ax += v * xv.x; ay += v * xv.y; az += v * xv.z; aw += v * xv.w;
    }
    ax = fmaxf(ax, 0.f); ay = fmaxf(ay, 0.f);
    az = fmaxf(az, 0.f); aw = fmaxf(aw, 0.f);
    if (do_norm) {
        float ss = ax * ax + ay * ay + az * az + aw * aw;
        #pragma unroll
        for (int o = 16; o; o >>= 1) ss += __shfl_xor_sync(0xffffffffu, ss, o);
        float inv = 1.0f / fmaxf(sqrtf(ss), 1e-12f);
        ax *= inv; ay *= inv; az *= inv; aw *= inv;
    }
    uint2 hv, lv;
    pack_hl(ax, ay, hv.x, lv.x);
    pack_hl(az, aw, hv.y, lv.y);
    size_t off = (size_t)row * HH + lane * 4;
    *(uint2*)(xh + off) = hv;
    *(uint2*)(xl + off) = lv;
}

__global__ void mul_kernel(const float* __restrict__ a, const float* __restrict__ b,
                           float* __restrict__ out, int M) {
    int i = blockIdx.x * blockDim.x + threadIdx.x;
    if (i < M) out[i] = a[i] * b[i];
}

// ---------------- pipelined mma.sync GEMM -------------------------------------
// C = A @ W ; A pre-split bf16 (Ah,Al) [M][K]; W pre-split bf16 [Ncol][K].
// 3-term Markidis: AhBh + AhBl + AlBh, fp32 accum.
// BM=128,BN=128,BK=32; 8 warps (2x4); cp.async 2-stage pipeline.
// Epilogues: (a) m3s!=0: fused scoring -> atomicAdd(sc)
//            (b) Ch!=0:  relu + split bf16 hi/lo write (h1)
//            (c) else:   fp32 C write (+optional relu)
#define BK 32
#define LDP 40                      // row stride elems: 80B, odd*16B -> ldmatrix conflict-free
#define STG_ELEMS (128 * LDP)       // per array per stage
#define GEMM_SMEM (2 * 4 * STG_ELEMS * 2)  // 81920 B

__global__ void __launch_bounds__(256, 1) tc_gemm_kernel(
    const __nv_bfloat16* __restrict__ Ah, const __nv_bfloat16* __restrict__ Al,
    const __nv_bfloat16* __restrict__ Bh, const __nv_bfloat16* __restrict__ Bl,
    const float* __restrict__ bias, float* __restrict__ C,
    __nv_bfloat16* __restrict__ Ch, __nv_bfloat16* __restrict__ Cl,
    int M, int K, int Ncol, int relu,
    const float* __restrict__ m3s, float* __restrict__ sc)
{
    extern __shared__ __align__(16) uint16_t smem[];
    const int tid = threadIdx.x;
    const int wid = tid >> 5, lane = tid & 31;
    const int mw = wid >> 2, nw = wid & 3;
    const int row0 = blockIdx.x * 128;
    const int n0 = blockIdx.y * 128;

    float acc[4][4][4] = {};
    const uint32_t sbase = smem_u32(smem);
    auto abase = [&](int stage, int arr) {
        return sbase + (uint32_t)(((stage << 2) + arr) * STG_ELEMS * 2);
    };

    auto load_chunk = [&](int c, int stage) {
        const int k0 = c * BK;
        #pragma unroll
        for (int i = 0; i < 2; i++) {
            int idx = tid + i * 256;
            int r = idx >> 2, q = idx & 3;
            uint32_t doff = (uint32_t)(r * LDP + q * 8) * 2;
            int grow = row0 + r;
            int pa = (grow < M) ? 16 : 0;
            int ga = grow < M ? grow : (M - 1);
            cpa16(abase(stage, 0) + doff, Ah + (size_t)ga * K + k0 + q * 8, pa);
            cpa16(abase(stage, 1) + doff, Al + (size_t)ga * K + k0 + q * 8, pa);
            cpa16(abase(stage, 2) + doff, Bh + (size_t)(n0 + r) * K + k0 + q * 8, 16);
            cpa16(abase(stage, 3) + doff, Bl + (size_t)(n0 + r) * K + k0 + q * 8, 16);
        }
    };

    const int a_row_sel = lane & 15;
    const int a_k_sel   = (lane >> 4) * 8;
    const int b_row_sel = (lane & 7) + ((lane >> 4) << 3);
    const int b_k_sel   = ((lane >> 3) & 1) * 8;

    const int nchunks = K / BK;
    load_chunk(0, 0);
    asm volatile("cp.async.commit_group;" ::: "memory");

    for (int c = 0; c < nchunks; c++) {
        if (c + 1 < nchunks) load_chunk(c + 1, (c + 1) & 1);
        asm volatile("cp.async.commit_group;" ::: "memory");
        asm volatile("cp.async.wait_group 1;" ::: "memory");
        __syncthreads();
        const int st = c & 1;
        const uint32_t sAh = abase(st, 0), sAl = abase(st, 1);
        const uint32_t sBh = abase(st, 2), sBl = abase(st, 3);
        #pragma unroll
        for (int ks = 0; ks < 2; ks++) {
            const int koff = ks * 16;
            uint32_t ah[4][4], al[4][4];
            #pragma unroll
            for (int mi = 0; mi < 4; mi++) {
                uint32_t off = (uint32_t)((mw * 64 + mi * 16 + a_row_sel) * LDP
                                          + koff + a_k_sel) * 2;
                ldmx4(ah[mi], sAh + off);
                ldmx4(al[mi], sAl + off);
            }
            uint32_t bh[2][4], bl[2][4];
            #pragma unroll
            for (int p = 0; p < 2; p++) {
                uint32_t off = (uint32_t)((nw * 32 + p * 16 + b_row_sel) * LDP
                                          + koff + b_k_sel) * 2;
                ldmx4(bh[p], sBh + off);
                ldmx4(bl[p], sBl + off);
            }
            #pragma unroll
            for (int mi = 0; mi < 4; mi++) {
                #pragma unroll
                for (int ni = 0; ni < 4; ni++) {
                    uint32_t b0h = bh[ni >> 1][(ni & 1) * 2], b1h = bh[ni >> 1][(ni & 1) * 2 + 1];
                    uint32_t b0l = bl[ni >> 1][(ni & 1) * 2], b1l = bl[ni >> 1][(ni & 1) * 2 + 1];
                    mma_bf16(acc[mi][ni], ah[mi], b0h, b1h);
                    mma_bf16(acc[mi][ni], ah[mi], b0l, b1l);
                    mma_bf16(acc[mi][ni], al[mi], b0h, b1h);
                }
            }
        }
        __syncthreads();
    }

    const int mrow = row0 + mw * 64 + (lane >> 2);
    const int ncol = n0 + nw * 32 + (lane & 3) * 2;

    if (m3s) {  // fused scoring
        #pragma unroll
        for (int mi = 0; mi < 4; mi++) {
            int r_lo = mrow + mi * 16;
            int r_hi = r_lo + 8;
            float plo = 0.f, phi = 0.f;
            #pragma unroll
            for (int ni = 0; ni < 4; ni++) {
                int col = ncol + ni * 8;
                float m30 = __ldg(m3s + col), m31 = __ldg(m3s + col + 1);
                float b0 = __ldg(bias + col), b1 = __ldg(bias + col + 1);
                plo += fmaxf(acc[mi][ni][0] + b0, 0.f) * m30
                     + fmaxf(acc[mi][ni][1] + b1, 0.f) * m31;
                phi += fmaxf(acc[mi][ni][2] + b0, 0.f) * m30
                     + fmaxf(acc[mi][ni][3] + b1, 0.f) * m31;
            }
            plo += __shfl_xor_sync(0xffffffffu, plo, 1);
            plo += __shfl_xor_sync(0xffffffffu, plo, 2);
            phi += __shfl_xor_sync(0xffffffffu, phi, 1);
            phi += __shfl_xor_sync(0xffffffffu, phi, 2);
            if ((lane & 3) == 0) {
                if (r_lo < M) atomicAdd(sc + r_lo, plo);
                if (r_hi < M) atomicAdd(sc + r_hi, phi);
            }
        }
        return;
    }

    if (Ch) {  // relu + bf16 hi/lo split write (h1 producer)
        #pragma unroll
        for (int mi = 0; mi < 4; mi++) {
            int r_lo = mrow + mi * 16;
            int r_hi = r_lo + 8;
            #pragma unroll
            for (int ni = 0; ni < 4; ni++) {
                int col = ncol + ni * 8;
                float b0 = bias ? __ldg(bias + col) : 0.f;
                float b1 = bias ? __ldg(bias + col + 1) : 0.f;
                float v0 = fmaxf(acc[mi][ni][0] + b0, 0.f);
                float v1 = fmaxf(acc[mi][ni][1] + b1, 0.f);
                float v2 = fmaxf(acc[mi][ni][2] + b0, 0.f);
                float v3 = fmaxf(acc[mi][ni][3] + b1, 0.f);
                uint32_t hu, lu;
                if (r_lo < M) {
                    pack_hl(v0, v1, hu, lu);
                    *(uint32_t*)(Ch + (size_t)r_lo * Ncol + col) = hu;
                    *(uint32_t*)(Cl + (size_t)r_lo * Ncol + col) = lu;
                }
                if (r_hi < M) {
                    pack_hl(v2, v3, hu, lu);
                    *(uint32_t*)(Ch + (size_t)r_hi * Ncol + col) = hu;
                    *(uint32_t*)(Cl + (size_t)r_hi * Ncol + col) = lu;
                }
            }
        }
        return;
    }

    #pragma unroll
    for (int mi = 0; mi < 4; mi++) {
        int r_lo = mrow + mi * 16;
        int r_hi = r_lo + 8;
        #pragma unroll
        for (int ni = 0; ni < 4; ni++) {
            int col = ncol + ni * 8;
            float v0 = acc[mi][ni][0], v1 = acc[mi][ni][1];
            float v2 = acc[mi][ni][2], v3 = acc[mi][ni][3];
            if (relu) {
                v0 = fmaxf(v0, 0.f); v1 = fmaxf(v1, 0.f);
                v2 = fmaxf(v2, 0.f); v3 = fmaxf(v3, 0.f);
            }
            if (r_lo < M) *(float2*)(C + (size_t)r_lo * Ncol + col) = make_float2(v0, v1);
            if (r_hi < M) *(float2*)(C + (size_t)r_hi * Ncol + col) = make_float2(v2, v3);
        }
    }
}

// ---------------- launch -----------------------------------------------------
extern "C" void kernel_launch(void* const* d_in, const int* in_sizes, int n_in,
                              void* d_out, int out_size) {
    const int*   adjr[2] = {(const int*)d_in[0], (const int*)d_in[3]};
    const int*   adjc[2] = {(const int*)d_in[1], (const int*)d_in[4]};
    const float* adjv[2] = {(const float*)d_in[2], (const float*)d_in[5]};
    const float* w1 = (const float*)d_in[6];
    const float* m1 = (const float*)d_in[15];
    const float* b1 = (const float*)d_in[16];
    const float* m2 = (const float*)d_in[17];
    const float* b2 = (const float*)d_in[18];
    const float* m3 = (const float*)d_in[19];
    const float* b3 = (const float*)d_in[20];
    float* out = (float*)d_out;

    const int E = in_sizes[0];
    const int M = in_sizes[6] / HH;

    __nv_bfloat16 *xh, *xl, *h1h, *h1l, *wth, *wtl;
    float *gt, *csv;
    float (*gs)[NN];
    int *rp, *cnt, *csc;
    cudaGetSymbolAddress((void**)&xh,  g_xh);
    cudaGetSymbolAddress((void**)&xl,  g_xl);
    cudaGetSymbolAddress((void**)&gt,  g_t);
    cudaGetSymbolAddress((void**)&h1h, g_h1h);
    cudaGetSymbolAddress((void**)&h1l, g_h1l);
    cudaGetSymbolAddress((void**)&gs,  g_s);
    cudaGetSymbolAddress((void**)&rp,  g_rp);
    cudaGetSymbolAddress((void**)&cnt, g_cnt);
    cudaGetSymbolAddress((void**)&csc, g_cols);
    cudaGetSymbolAddress((void**)&csv, g_vals);
    cudaGetSymbolAddress((void**)&wth, g_wth);
    cudaGetSymbolAddress((void**)&wtl, g_wtl);

    cudaFuncSetAttribute(tc_gemm_kernel,
                         cudaFuncAttributeMaxDynamicSharedMemorySize, GEMM_SMEM);

    // launch #0: all weight conversions + cnt zeroing (one kernel)
    ConvSrcs cs;
    for (int i = 0; i < 8; i++) cs.p[i] = (const float*)d_in[7 + i];
    cs.p[8] = m1; cs.p[9] = m2;
    {
        int tot = (int)WT_TOTAL + NN;
        conv_all_kernel<<<(tot + 255) / 256, 256>>>(cs, wth, wtl, cnt);
    }

    const int warpBlocks = (int)(((long long)M * 32 + 255) / 256);
    const int eBlocks = (E + 255) / 256;
    const int nBlocks = (M + 255) / 256;
    const int mtiles = (M + 127) / 128;
    dim3 g_w(mtiles, 1);
    dim3 g_m(mtiles, 2);

    for (int b = 0; b < 2; b++) {
        if (b) zero_int_kernel<<<nBlocks, 256>>>(cnt, M);        // cnt reused
        hist_kernel<<<eBlocks, 256>>>(adjr[b], cnt, E);          // #1
        scan_kernel<<<1, 1024>>>(cnt, rp, cnt, M);               // #2 (rp + cursor)
        scatter_kernel<<<eBlocks, 256>>>(adjr[b], adjc[b], adjv[b], cnt, csc, csv,
                                         E, gs[b], b3, M);       // #3
        // layer 0: x = l2norm(relu(A @ w1)), split bf16
        spmm_csr_kernel<<<warpBlocks, 256>>>(rp, csc, csv, w1, xh, xl, M, 1);  // #4

        for (int L = 0; L <= 8; L++) {
            // MLP scoring (m1: split h1 producer; m2: fused scoring epilogue)
            tc_gemm_kernel<<<g_m, 256, GEMM_SMEM>>>(xh, xl, wth + WT_M1, wtl + WT_M1,
                                                    b1, nullptr, h1h, h1l,
                                                    M, HH, HD2, 1, nullptr, nullptr);  // #5
            tc_gemm_kernel<<<g_m, 256, GEMM_SMEM>>>(h1h, h1l, wth + WT_M2, wtl + WT_M2,
                                                    b2, nullptr, nullptr, nullptr,
                                                    M, HD2, HD2, 1, m3, gs[b]);
            if (L < 8) {
                tc_gemm_kernel<<<g_w, 256, GEMM_SMEM>>>(xh, xl, wth + WT_W(L), wtl + WT_W(L),
                                                        nullptr, gt, nullptr, nullptr,
                                                        M, HH, HH, 0, nullptr, nullptr);
                spmm_csr_kernel<<<warpBlocks, 256>>>(rp, csc, csv, gt, xh, xl, M,
                                                     (L + 1 < 8) ? 1 : 0);
            }
        }
    }

    mul_kernel<<<nBlocks, 256>>>(gs[0], gs[1], out, M);
}

// round 8
// speedup vs baseline: 2.4942x; 1.0045x over previous
#include <cuda_runtime.h>
#include <cuda_bf16.h>
#include <math.h>
#include <cstdint>

#define NN 100000
#define EE 1600000
#define HH 128
#define HD2 256

// ---------------- scratch (__device__ globals) -------------------------------
__device__ __nv_bfloat16 g_xh [(size_t)NN * HH];   // x hi
__device__ __nv_bfloat16 g_xl [(size_t)NN * HH];   // x lo
__device__ float         g_t  [(size_t)NN * HH];   // x @ w (fp32, spmm input)
__device__ __nv_bfloat16 g_h1h[(size_t)NN * HD2];  // mlp hidden hi
__device__ __nv_bfloat16 g_h1l[(size_t)NN * HD2];  // mlp hidden lo
__device__ float g_s[2][NN];
__device__ int   g_rp  [NN + 1];
__device__ int   g_cnt [NN];
__device__ int   g_cols[EE];
__device__ float g_vals[EE];

// transposed bf16-split weights, layout [n][k] (k contiguous) == mma "col"
#define WT_W(i)  ((size_t)(i) * 16384)
#define WT_M1    ((size_t)8 * 16384)
#define WT_M2    (WT_M1 + 32768)
#define WT_TOTAL (WT_M2 + 65536)
__device__ __nv_bfloat16 g_wth[WT_TOTAL];
__device__ __nv_bfloat16 g_wtl[WT_TOTAL];

// ---------------- helpers ----------------------------------------------------
__device__ __forceinline__ uint32_t smem_u32(const void* p) {
    uint32_t a;
    asm("{ .reg .u64 t; cvta.to.shared.u64 t, %1; cvt.u32.u64 %0, t; }" : "=r"(a) : "l"(p));
    return a;
}
__device__ __forceinline__ void ldmx4(uint32_t* r, uint32_t addr) {
    asm volatile("ldmatrix.sync.aligned.m8n8.x4.shared.b16 {%0,%1,%2,%3}, [%4];"
                 : "=r"(r[0]), "=r"(r[1]), "=r"(r[2]), "=r"(r[3]) : "r"(addr));
}
__device__ __forceinline__ void mma_bf16(float* c, const uint32_t* a, uint32_t b0, uint32_t b1) {
    asm volatile(
        "mma.sync.aligned.m16n8k16.row.col.f32.bf16.bf16.f32 "
        "{%0,%1,%2,%3}, {%4,%5,%6,%7}, {%8,%9}, {%0,%1,%2,%3};"
        : "+f"(c[0]), "+f"(c[1]), "+f"(c[2]), "+f"(c[3])
        : "r"(a[0]), "r"(a[1]), "r"(a[2]), "r"(a[3]), "r"(b0), "r"(b1));
}
__device__ __forceinline__ void cpa16(uint32_t dst, const void* src, int nbytes) {
    asm volatile("cp.async.cg.shared.global [%0], [%1], 16, %2;"
                 :: "r"(dst), "l"(src), "r"(nbytes) : "memory");
}
__device__ __forceinline__ void pack_hl(float a, float b, uint32_t& hu, uint32_t& lu) {
    __nv_bfloat16 ha = __float2bfloat16(a), hb = __float2bfloat16(b);
    __nv_bfloat16 la = __float2bfloat16(a - __bfloat162float(ha));
    __nv_bfloat16 lb = __float2bfloat16(b - __bfloat162float(hb));
    hu = (uint32_t)__bfloat16_as_ushort(ha) | ((uint32_t)__bfloat16_as_ushort(hb) << 16);
    lu = (uint32_t)__bfloat16_as_ushort(la) | ((uint32_t)__bfloat16_as_ushort(lb) << 16);
}

// ---------------- fused preprocessing ----------------------------------------
struct ConvSrcs { const float* p[10]; };

__global__ void conv_all_kernel(ConvSrcs srcs, __nv_bfloat16* __restrict__ oh,
                                __nv_bfloat16* __restrict__ ol, int* __restrict__ cnt) {
    int gid = blockIdx.x * blockDim.x + threadIdx.x;
    if (gid < (int)WT_TOTAL) {
        const float* W; int local, K, Ncol;
        if (gid < 131072)               { W = srcs.p[gid >> 14]; local = gid & 16383;            K = HH;  Ncol = HH;  }
        else if (gid < 131072 + 32768)  { W = srcs.p[8];         local = gid - 131072;           K = HH;  Ncol = HD2; }
        else                            { W = srcs.p[9];         local = gid - (131072 + 32768); K = HD2; Ncol = HD2; }
        int n = local / K, k = local - n * K;
        float v = W[(size_t)k * Ncol + n];
        __nv_bfloat16 h = __float2bfloat16(v);
        oh[gid] = h;
        ol[gid] = __float2bfloat16(v - __bfloat162float(h));
    } else {
        int j = gid - (int)WT_TOTAL;
        if (j < NN) cnt[j] = 0;
    }
}

__global__ void zero_int_kernel(int* __restrict__ p, int n) {
    int i = blockIdx.x * blockDim.x + threadIdx.x;
    if (i < n) p[i] = 0;
}

__global__ void hist_kernel(const int* __restrict__ rows, int* __restrict__ cnt, int nE) {
    int e = blockIdx.x * blockDim.x + threadIdx.x;
    if (e < nE) atomicAdd(&cnt[rows[e]], 1);
}

// single-block scan: rp[0]=0, rp[i+1]=incl(i), cur[i]=rp[i]
__global__ void scan_kernel(const int* __restrict__ cnt, int* __restrict__ rp,
                            int* __restrict__ cur, int n) {
    __shared__ int sdata[1024];
    __shared__ int carry;
    int tid = threadIdx.x;
    if (tid == 0) { carry = 0; rp[0] = 0; }
    __syncthreads();
    for (int base = 0; base < n; base += 1024) {
        int i = base + tid;
        int v = (i < n) ? cnt[i] : 0;
        sdata[tid] = v;
        __syncthreads();
        #pragma unroll
        for (int o = 1; o < 1024; o <<= 1) {
            int t = sdata[tid];
            if (tid >= o) t += sdata[tid - o];
            __syncthreads();
            sdata[tid] = t;
            __syncthreads();
        }
        if (i < n) {
            int incl = carry + sdata[tid];
            rp[i + 1] = incl;
            cur[i] = incl - v;
        }
        __syncthreads();
        if (tid == 0) carry += sdata[1023];
        __syncthreads();
    }
}

// scatter + score init (score = 9*b3 since mlp adds b3 nine times)
__global__ void scatter_kernel(const int* __restrict__ rows, const int* __restrict__ cols,
                               const float* __restrict__ vals, int* __restrict__ cur,
                               int* __restrict__ cs, float* __restrict__ vs, int nE,
                               float* __restrict__ s, const float* __restrict__ b3, int M) {
    int e = blockIdx.x * blockDim.x + threadIdx.x;
    if (e < M) s[e] = 9.0f * b3[0];
    if (e >= nE) return;
    int pos = atomicAdd(&cur[rows[e]], 1);
    cs[pos] = cols[e];
    vs[pos] = vals[e];
}

// ---------------- CSR SpMM fused relu(+norm), bf16 hi/lo split output --------
__global__ void spmm_csr_kernel(const int* __restrict__ rp, const int* __restrict__ cs,
                                const float* __restrict__ vs, const float* __restrict__ xin,
                                __nv_bfloat16* __restrict__ xh, __nv_bfloat16* __restrict__ xl,
                                int M, int do_norm) {
    long long idx = (long long)blockIdx.x * blockDim.x + threadIdx.x;
    int row = (int)(idx >> 5);
    if (row >= M) return;
    int lane = (int)(idx & 31);
    int s = __ldg(rp + row), e = __ldg(rp + row + 1);
    float ax = 0.f, ay = 0.f, az = 0.f, aw = 0.f;
    for (int j = s; j < e; j++) {
        int c = __ldg(cs + j);
        float v = __ldg(vs + j);
        float4 xv = *(const float4*)(xin + (size_t)c * HH + lane * 4);
        ax += v * xv.x; ay += v * xv.y; az += v * xv.z; aw += v * xv.w;
    }
    ax = fmaxf(ax, 0.f); ay = fmaxf(ay, 0.f);
    az = fmaxf(az, 0.f); aw = fmaxf(aw, 0.f);
    if (do_norm) {
        float ss = ax * ax + ay * ay + az * az + aw * aw;
        #pragma unroll
        for (int o = 16; o; o >>= 1) ss += __shfl_xor_sync(0xffffffffu, ss, o);
        float inv = 1.0f / fmaxf(sqrtf(ss), 1e-12f);
        ax *= inv; ay *= inv; az *= inv; aw *= inv;
    }
    uint2 hv, lv;
    pack_hl(ax, ay, hv.x, lv.x);
    pack_hl(az, aw, hv.y, lv.y);
    size_t off = (size_t)row * HH + lane * 4;
    *(uint2*)(xh + off) = hv;
    *(uint2*)(xl + off) = lv;
}

__global__ void mul_kernel(const float* __restrict__ a, const float* __restrict__ b,
                           float* __restrict__ out, int M) {
    int i = blockIdx.x * blockDim.x + threadIdx.x;
    if (i < M) out[i] = a[i] * b[i];
}

// ---------------- pipelined mma.sync GEMM -------------------------------------
// C = A @ W ; A pre-split bf16 (Ah,Al) [M][K]; W pre-split bf16 [Ncol][K].
// 3-term Markidis: AhBh + AhBl + AlBh, fp32 accum.
// BM=128,BN=128,BK=32; 8 warps (2x4); cp.async 2-stage pipeline.
// Epilogues: (a) m3s!=0: fused scoring -> atomicAdd(sc)
//            (b) Ch!=0:  relu + split bf16 hi/lo write (h1)
//            (c) else:   fp32 C write (+optional relu)
#define BK 32
#define LDP 40                      // row stride elems: 80B, odd*16B -> ldmatrix conflict-free
#define STG_ELEMS (128 * LDP)       // per array per stage
#define GEMM_SMEM (2 * 4 * STG_ELEMS * 2)  // 81920 B

__global__ void __launch_bounds__(256, 1) tc_gemm_kernel(
    const __nv_bfloat16* __restrict__ Ah, const __nv_bfloat16* __restrict__ Al,
    const __nv_bfloat16* __restrict__ Bh, const __nv_bfloat16* __restrict__ Bl,
    const float* __restrict__ bias, float* __restrict__ C,
    __nv_bfloat16* __restrict__ Ch, __nv_bfloat16* __restrict__ Cl,
    int M, int K, int Ncol, int relu,
    const float* __restrict__ m3s, float* __restrict__ sc)
{
    extern __shared__ __align__(16) uint16_t smem[];
    const int tid = threadIdx.x;
    const int wid = tid >> 5, lane = tid & 31;
    const int mw = wid >> 2, nw = wid & 3;
    const int row0 = blockIdx.x * 128;
    const int n0 = blockIdx.y * 128;

    float acc[4][4][4] = {};
    const uint32_t sbase = smem_u32(smem);
    auto abase = [&](int stage, int arr) {
        return sbase + (uint32_t)(((stage << 2) + arr) * STG_ELEMS * 2);
    };

    auto load_chunk = [&](int c, int stage) {
        const int k0 = c * BK;
        #pragma unroll
        for (int i = 0; i < 2; i++) {
            int idx = tid + i * 256;
            int r = idx >> 2, q = idx & 3;
            uint32_t doff = (uint32_t)(r * LDP + q * 8) * 2;
            int grow = row0 + r;
            int pa = (grow < M) ? 16 : 0;
            int ga = grow < M ? grow : (M - 1);
            cpa16(abase(stage, 0) + doff, Ah + (size_t)ga * K + k0 + q * 8, pa);
            cpa16(abase(stage, 1) + doff, Al + (size_t)ga * K + k0 + q * 8, pa);
            cpa16(abase(stage, 2) + doff, Bh + (size_t)(n0 + r) * K + k0 + q * 8, 16);
            cpa16(abase(stage, 3) + doff, Bl + (size_t)(n0 + r) * K + k0 + q * 8, 16);
        }
    };

    const int a_row_sel = lane & 15;
    const int a_k_sel   = (lane >> 4) * 8;
    const int b_row_sel = (lane & 7) + ((lane >> 4) << 3);
    const int b_k_sel   = ((lane >> 3) & 1) * 8;

    const int nchunks = K / BK;
    load_chunk(0, 0);
    asm volatile("cp.async.commit_group;" ::: "memory");

    for (int c = 0; c < nchunks; c++) {
        if (c + 1 < nchunks) load_chunk(c + 1, (c + 1) & 1);
        asm volatile("cp.async.commit_group;" ::: "memory");
        asm volatile("cp.async.wait_group 1;" ::: "memory");
        __syncthreads();
        const int st = c & 1;
        const uint32_t sAh = abase(st, 0), sAl = abase(st, 1);
        const uint32_t sBh = abase(st, 2), sBl = abase(st, 3);
        #pragma unroll
        for (int ks = 0; ks < 2; ks++) {
            const int koff = ks * 16;
            uint32_t ah[4][4], al[4][4];
            #pragma unroll
            for (int mi = 0; mi < 4; mi++) {
                uint32_t off = (uint32_t)((mw * 64 + mi * 16 + a_row_sel) * LDP
                                          + koff + a_k_sel) * 2;
                ldmx4(ah[mi], sAh + off);
                ldmx4(al[mi], sAl + off);
            }
            uint32_t bh[2][4], bl[2][4];
            #pragma unroll
            for (int p = 0; p < 2; p++) {
                uint32_t off = (uint32_t)((nw * 32 + p * 16 + b_row_sel) * LDP
                                          + koff + b_k_sel) * 2;
                ldmx4(bh[p], sBh + off);
                ldmx4(bl[p], sBl + off);
            }
            #pragma unroll
            for (int mi = 0; mi < 4; mi++) {
                #pragma unroll
                for (int ni = 0; ni < 4; ni++) {
                    uint32_t b0h = bh[ni >> 1][(ni & 1) * 2], b1h = bh[ni >> 1][(ni & 1) * 2 + 1];
                    uint32_t b0l = bl[ni >> 1][(ni & 1) * 2], b1l = bl[ni >> 1][(ni & 1) * 2 + 1];
                    mma_bf16(acc[mi][ni], ah[mi], b0h, b1h);
                    mma_bf16(acc[mi][ni], ah[mi], b0l, b1l);
                    mma_bf16(acc[mi][ni], al[mi], b0h, b1h);
                }
            }
        }
        __syncthreads();
    }

    const int mrow = row0 + mw * 64 + (lane >> 2);
    const int ncol = n0 + nw * 32 + (lane & 3) * 2;

    if (m3s) {  // fused scoring
        #pragma unroll
        for (int mi = 0; mi < 4; mi++) {
            int r_lo = mrow + mi * 16;
            int r_hi = r_lo + 8;
            float plo = 0.f, phi = 0.f;
            #pragma unroll
            for (int ni = 0; ni < 4; ni++) {
                int col = ncol + ni * 8;
                float m30 = __ldg(m3s + col), m31 = __ldg(m3s + col + 1);
                float b0 = __ldg(bias + col), b1 = __ldg(bias + col + 1);
                plo += fmaxf(acc[mi][ni][0] + b0, 0.f) * m30
                     + fmaxf(acc[mi][ni][1] + b1, 0.f) * m31;
                phi += fmaxf(acc[mi][ni][2] + b0, 0.f) * m30
                     + fmaxf(acc[mi][ni][3] + b1, 0.f) * m31;
            }
            plo += __shfl_xor_sync(0xffffffffu, plo, 1);
            plo += __shfl_xor_sync(0xffffffffu, plo, 2);
            phi += __shfl_xor_sync(0xffffffffu, phi, 1);
            phi += __shfl_xor_sync(0xffffffffu, phi, 2);
            if ((lane & 3) == 0) {
                if (r_lo < M) atomicAdd(sc + r_lo, plo);
                if (r_hi < M) atomicAdd(sc + r_hi, phi);
            }
        }
        return;
    }

    if (Ch) {  // relu + bf16 hi/lo split write (h1 producer)
        #pragma unroll
        for (int mi = 0; mi < 4; mi++) {
            int r_lo = mrow + mi * 16;
            int r_hi = r_lo + 8;
            #pragma unroll
            for (int ni = 0; ni < 4; ni++) {
                int col = ncol + ni * 8;
                float b0 = bias ? __ldg(bias + col) : 0.f;
                float b1 = bias ? __ldg(bias + col + 1) : 0.f;
                float v0 = fmaxf(acc[mi][ni][0] + b0, 0.f);
                float v1 = fmaxf(acc[mi][ni][1] + b1, 0.f);
                float v2 = fmaxf(acc[mi][ni][2] + b0, 0.f);
                float v3 = fmaxf(acc[mi][ni][3] + b1, 0.f);
                uint32_t hu, lu;
                if (r_lo < M) {
                    pack_hl(v0, v1, hu, lu);
                    *(uint32_t*)(Ch + (size_t)r_lo * Ncol + col) = hu;
                    *(uint32_t*)(Cl + (size_t)r_lo * Ncol + col) = lu;
                }
                if (r_hi < M) {
                    pack_hl(v2, v3, hu, lu);
                    *(uint32_t*)(Ch + (size_t)r_hi * Ncol + col) = hu;
                    *(uint32_t*)(Cl + (size_t)r_hi * Ncol + col) = lu;
                }
            }
        }
        return;
    }

    #pragma unroll
    for (int mi = 0; mi < 4; mi++) {
        int r_lo = mrow + mi * 16;
        int r_hi = r_lo + 8;
        #pragma unroll
        for (int ni = 0; ni < 4; ni++) {
            int col = ncol + ni * 8;
            float v0 = acc[mi][ni][0], v1 = acc[mi][ni][1];
            float v2 = acc[mi][ni][2], v3 = acc[mi][ni][3];
            if (relu) {
                v0 = fmaxf(v0, 0.f); v1 = fmaxf(v1, 0.f);
                v2 = fmaxf(v2, 0.f); v3 = fmaxf(v3, 0.f);
            }
            if (r_lo < M) *(float2*)(C + (size_t)r_lo * Ncol + col) = make_float2(v0, v1);
            if (r_hi < M) *(float2*)(C + (size_t)r_hi * Ncol + col) = make_float2(v2, v3);
        }
    }
}

// ---------------- launch -----------------------------------------------------
extern "C" void kernel_launch(void* const* d_in, const int* in_sizes, int n_in,
                              void* d_out, int out_size) {
    const int*   adjr[2] = {(const int*)d_in[0], (const int*)d_in[3]};
    const int*   adjc[2] = {(const int*)d_in[1], (const int*)d_in[4]};
    const float* adjv[2] = {(const float*)d_in[2], (const float*)d_in[5]};
    const float* w1 = (const float*)d_in[6];
    const float* m1 = (const float*)d_in[15];
    const float* b1 = (const float*)d_in[16];
    const float* m2 = (const float*)d_in[17];
    const float* b2 = (const float*)d_in[18];
    const float* m3 = (const float*)d_in[19];
    const float* b3 = (const float*)d_in[20];
    float* out = (float*)d_out;

    const int E = in_sizes[0];
    const int M = in_sizes[6] / HH;

    __nv_bfloat16 *xh, *xl, *h1h, *h1l, *wth, *wtl;
    float *gt, *csv;
    float (*gs)[NN];
    int *rp, *cnt, *csc;
    cudaGetSymbolAddress((void**)&xh,  g_xh);
    cudaGetSymbolAddress((void**)&xl,  g_xl);
    cudaGetSymbolAddress((void**)&gt,  g_t);
    cudaGetSymbolAddress((void**)&h1h, g_h1h);
    cudaGetSymbolAddress((void**)&h1l, g_h1l);
    cudaGetSymbolAddress((void**)&gs,  g_s);
    cudaGetSymbolAddress((void**)&rp,  g_rp);
    cudaGetSymbolAddress((void**)&cnt, g_cnt);
    cudaGetSymbolAddress((void**)&csc, g_cols);
    cudaGetSymbolAddress((void**)&csv, g_vals);
    cudaGetSymbolAddress((void**)&wth, g_wth);
    cudaGetSymbolAddress((void**)&wtl, g_wtl);

    cudaFuncSetAttribute(tc_gemm_kernel,
                         cudaFuncAttributeMaxDynamicSharedMemorySize, GEMM_SMEM);

    // launch #0: all weight conversions + cnt zeroing (one kernel)
    ConvSrcs cs;
    for (int i = 0; i < 8; i++) cs.p[i] = (const float*)d_in[7 + i];
    cs.p[8] = m1; cs.p[9] = m2;
    {
        int tot = (int)WT_TOTAL + NN;
        conv_all_kernel<<<(tot + 255) / 256, 256>>>(cs, wth, wtl, cnt);
    }

    const int warpBlocks = (int)(((long long)M * 32 + 255) / 256);
    const int eBlocks = (E + 255) / 256;
    const int nBlocks = (M + 255) / 256;
    const int mtiles = (M + 127) / 128;
    dim3 g_w(mtiles, 1);
    dim3 g_m(mtiles, 2);

    for (int b = 0; b < 2; b++) {
        if (b) zero_int_kernel<<<nBlocks, 256>>>(cnt, M);        // cnt reused
        hist_kernel<<<eBlocks, 256>>>(adjr[b], cnt, E);          // #1
        scan_kernel<<<1, 1024>>>(cnt, rp, cnt, M);               // #2 (rp + cursor)
        scatter_kernel<<<eBlocks, 256>>>(adjr[b], adjc[b], adjv[b], cnt, csc, csv,
                                         E, gs[b], b3, M);       // #3
        // layer 0: x = l2norm(relu(A @ w1)), split bf16
        spmm_csr_kernel<<<warpBlocks, 256>>>(rp, csc, csv, w1, xh, xl, M, 1);  // #4

        for (int L = 0; L <= 8; L++) {
            // MLP scoring (m1: split h1 producer; m2: fused scoring epilogue)
            tc_gemm_kernel<<<g_m, 256, GEMM_SMEM>>>(xh, xl, wth + WT_M1, wtl + WT_M1,
                                                    b1, nullptr, h1h, h1l,
                                                    M, HH, HD2, 1, nullptr, nullptr);  // #5
            tc_gemm_kernel<<<g_m, 256, GEMM_SMEM>>>(h1h, h1l, wth + WT_M2, wtl + WT_M2,
                                                    b2, nullptr, nullptr, nullptr,
                                                    M, HD2, HD2, 1, m3, gs[b]);
            if (L < 8) {
                tc_gemm_kernel<<<g_w, 256, GEMM_SMEM>>>(xh, xl, wth + WT_W(L), wtl + WT_W(L),
                                                        nullptr, gt, nullptr, nullptr,
                                                        M, HH, HH, 0, nullptr, nullptr);
                spmm_csr_kernel<<<warpBlocks, 256>>>(rp, csc, csv, gt, xh, xl, M,
                                                     (L + 1 < 8) ? 1 : 0);
            }
        }
    }

    mul_kernel<<<nBlocks, 256>>>(gs[0], gs[1], out, M);
}

// round 9
// speedup vs baseline: 2.4973x; 1.0013x over previous
#include <cuda_runtime.h>
#include <cuda_bf16.h>
#include <math.h>
#include <cstdint>

#define NN 100000
#define EE 1600000
#define HH 128
#define HD2 256

// ---------------- scratch (__device__ globals) -------------------------------
__device__ __nv_bfloat16 g_xh [(size_t)NN * HH];   // x hi
__device__ __nv_bfloat16 g_xl [(size_t)NN * HH];   // x lo
__device__ float         g_t  [(size_t)NN * HH];   // x @ w (fp32, spmm input)
__device__ __nv_bfloat16 g_h1h[(size_t)NN * HD2];  // mlp hidden hi
__device__ __nv_bfloat16 g_h1l[(size_t)NN * HD2];  // mlp hidden lo
__device__ float g_s[2][NN];
__device__ int   g_rp  [NN + 1];
__device__ int   g_cnt [NN];
__device__ int   g_cols[EE];
__device__ float g_vals[EE];

// transposed bf16-split weights, layout [n][k] (k contiguous) == mma "col"
#define WT_W(i)  ((size_t)(i) * 16384)
#define WT_M1    ((size_t)8 * 16384)
#define WT_M2    (WT_M1 + 32768)
#define WT_TOTAL (WT_M2 + 65536)
__device__ __nv_bfloat16 g_wth[WT_TOTAL];
__device__ __nv_bfloat16 g_wtl[WT_TOTAL];

// ---------------- helpers ----------------------------------------------------
__device__ __forceinline__ uint32_t smem_u32(const void* p) {
    uint32_t a;
    asm("{ .reg .u64 t; cvta.to.shared.u64 t, %1; cvt.u32.u64 %0, t; }" : "=r"(a) : "l"(p));
    return a;
}
__device__ __forceinline__ void ldmx4(uint32_t* r, uint32_t addr) {
    asm volatile("ldmatrix.sync.aligned.m8n8.x4.shared.b16 {%0,%1,%2,%3}, [%4];"
                 : "=r"(r[0]), "=r"(r[1]), "=r"(r[2]), "=r"(r[3]) : "r"(addr));
}
__device__ __forceinline__ void mma_bf16(float* c, const uint32_t* a, uint32_t b0, uint32_t b1) {
    asm volatile(
        "mma.sync.aligned.m16n8k16.row.col.f32.bf16.bf16.f32 "
        "{%0,%1,%2,%3}, {%4,%5,%6,%7}, {%8,%9}, {%0,%1,%2,%3};"
        : "+f"(c[0]), "+f"(c[1]), "+f"(c[2]), "+f"(c[3])
        : "r"(a[0]), "r"(a[1]), "r"(a[2]), "r"(a[3]), "r"(b0), "r"(b1));
}
__device__ __forceinline__ void cpa16(uint32_t dst, const void* src, int nbytes) {
    asm volatile("cp.async.cg.shared.global [%0], [%1], 16, %2;"
                 :: "r"(dst), "l"(src), "r"(nbytes) : "memory");
}
__device__ __forceinline__ void pack_hl(float a, float b, uint32_t& hu, uint32_t& lu) {
    __nv_bfloat16 ha = __float2bfloat16(a), hb = __float2bfloat16(b);
    __nv_bfloat16 la = __float2bfloat16(a - __bfloat162float(ha));
    __nv_bfloat16 lb = __float2bfloat16(b - __bfloat162float(hb));
    hu = (uint32_t)__bfloat16_as_ushort(ha) | ((uint32_t)__bfloat16_as_ushort(hb) << 16);
    lu = (uint32_t)__bfloat16_as_ushort(la) | ((uint32_t)__bfloat16_as_ushort(lb) << 16);
}

// ---------------- fused preprocessing ----------------------------------------
struct ConvSrcs { const float* p[10]; };

__global__ void conv_all_kernel(ConvSrcs srcs, __nv_bfloat16* __restrict__ oh,
                                __nv_bfloat16* __restrict__ ol, int* __restrict__ cnt) {
    int gid = blockIdx.x * blockDim.x + threadIdx.x;
    if (gid < (int)WT_TOTAL) {
        const float* W; int local, K, Ncol;
        if (gid < 131072)               { W = srcs.p[gid >> 14]; local = gid & 16383;            K = HH;  Ncol = HH;  }
        else if (gid < 131072 + 32768)  { W = srcs.p[8];         local = gid - 131072;           K = HH;  Ncol = HD2; }
        else                            { W = srcs.p[9];         local = gid - (131072 + 32768); K = HD2; Ncol = HD2; }
        int n = local / K, k = local - n * K;
        float v = W[(size_t)k * Ncol + n];
        __nv_bfloat16 h = __float2bfloat16(v);
        oh[gid] = h;
        ol[gid] = __float2bfloat16(v - __bfloat162float(h));
    } else {
        int j = gid - (int)WT_TOTAL;
        if (j < NN) cnt[j] = 0;
    }
}

__global__ void zero_int_kernel(int* __restrict__ p, int n) {
    int i = blockIdx.x * blockDim.x + threadIdx.x;
    if (i < n) p[i] = 0;
}

__global__ void hist_kernel(const int* __restrict__ rows, int* __restrict__ cnt, int nE) {
    int e = blockIdx.x * blockDim.x + threadIdx.x;
    if (e < nE) atomicAdd(&cnt[rows[e]], 1);
}

// single-block scan: rp[0]=0, rp[i+1]=incl(i), cur[i]=rp[i]
__global__ void scan_kernel(const int* __restrict__ cnt, int* __restrict__ rp,
                            int* __restrict__ cur, int n) {
    __shared__ int sdata[1024];
    __shared__ int carry;
    int tid = threadIdx.x;
    if (tid == 0) { carry = 0; rp[0] = 0; }
    __syncthreads();
    for (int base = 0; base < n; base += 1024) {
        int i = base + tid;
        int v = (i < n) ? cnt[i] : 0;
        sdata[tid] = v;
        __syncthreads();
        #pragma unroll
        for (int o = 1; o < 1024; o <<= 1) {
            int t = sdata[tid];
            if (tid >= o) t += sdata[tid - o];
            __syncthreads();
            sdata[tid] = t;
            __syncthreads();
        }
        if (i < n) {
            int incl = carry + sdata[tid];
            rp[i + 1] = incl;
            cur[i] = incl - v;
        }
        __syncthreads();
        if (tid == 0) carry += sdata[1023];
        __syncthreads();
    }
}

// scatter + score init (score = 9*b3 since mlp adds b3 nine times)
__global__ void scatter_kernel(const int* __restrict__ rows, const int* __restrict__ cols,
                               const float* __restrict__ vals, int* __restrict__ cur,
                               int* __restrict__ cs, float* __restrict__ vs, int nE,
                               float* __restrict__ s, const float* __restrict__ b3, int M) {
    int e = blockIdx.x * blockDim.x + threadIdx.x;
    if (e < M) s[e] = 9.0f * b3[0];
    if (e >= nE) return;
    int pos = atomicAdd(&cur[rows[e]], 1);
    cs[pos] = cols[e];
    vs[pos] = vals[e];
}

// ---------------- CSR SpMM fused relu(+norm), bf16 hi/lo split output --------
__global__ void spmm_csr_kernel(const int* __restrict__ rp, const int* __restrict__ cs,
                                const float* __restrict__ vs, const float* __restrict__ xin,
                                __nv_bfloat16* __restrict__ xh, __nv_bfloat16* __restrict__ xl,
                                int M, int do_norm) {
    long long idx = (long long)blockIdx.x * blockDim.x + threadIdx.x;
    int row = (int)(idx >> 5);
    if (row >= M) return;
    int lane = (int)(idx & 31);
    int s = __ldg(rp + row), e = __ldg(rp + row + 1);
    float ax = 0.f, ay = 0.f, az = 0.f, aw = 0.f;
    for (int j = s; j < e; j++) {
        int c = __ldg(cs + j);
        float v = __ldg(vs + j);
        float4 xv = *(const float4*)(xin + (size_t)c * HH + lane * 4);
        ax += v * xv.x; ay += v * xv.y; az += v * xv.z; aw += v * xv.w;
    }
    ax = fmaxf(ax, 0.f); ay = fmaxf(ay, 0.f);
    az = fmaxf(az, 0.f); aw = fmaxf(aw, 0.f);
    if (do_norm) {
        float ss = ax * ax + ay * ay + az * az + aw * aw;
        #pragma unroll
        for (int o = 16; o; o >>= 1) ss += __shfl_xor_sync(0xffffffffu, ss, o);
        float inv = 1.0f / fmaxf(sqrtf(ss), 1e-12f);
        ax *= inv; ay *= inv; az *= inv; aw *= inv;
    }
    uint2 hv, lv;
    pack_hl(ax, ay, hv.x, lv.x);
    pack_hl(az, aw, hv.y, lv.y);
    size_t off = (size_t)row * HH + lane * 4;
    *(uint2*)(xh + off) = hv;
    *(uint2*)(xl + off) = lv;
}

__global__ void mul_kernel(const float* __restrict__ a, const float* __restrict__ b,
                           float* __restrict__ out, int M) {
    int i = blockIdx.x * blockDim.x + threadIdx.x;
    if (i < M) out[i] = a[i] * b[i];
}

// ---------------- pipelined mma.sync GEMM -------------------------------------
// C = A @ W ; A pre-split bf16 (Ah,Al) [M][K]; W pre-split bf16 [Ncol][K].
// 3-term Markidis: AhBh + AhBl + AlBh, fp32 accum.
// BM=128,BN=128,BK=32; 8 warps (2x4); cp.async 2-stage pipeline.
// Epilogues: (a) m3s!=0: fused scoring -> atomicAdd(sc)
//            (b) Ch!=0:  relu + split bf16 hi/lo write (h1)
//            (c) else:   fp32 C write (+optional relu)
#define BK 32
#define LDP 40                      // row stride elems: 80B, odd*16B -> ldmatrix conflict-free
#define STG_ELEMS (128 * LDP)       // per array per stage
#define GEMM_SMEM (2 * 4 * STG_ELEMS * 2)  // 81920 B

__global__ void __launch_bounds__(256, 1) tc_gemm_kernel(
    const __nv_bfloat16* __restrict__ Ah, const __nv_bfloat16* __restrict__ Al,
    const __nv_bfloat16* __restrict__ Bh, const __nv_bfloat16* __restrict__ Bl,
    const float* __restrict__ bias, float* __restrict__ C,
    __nv_bfloat16* __restrict__ Ch, __nv_bfloat16* __restrict__ Cl,
    int M, int K, int Ncol, int relu,
    const float* __restrict__ m3s, float* __restrict__ sc)
{
    extern __shared__ __align__(16) uint16_t smem[];
    const int tid = threadIdx.x;
    const int wid = tid >> 5, lane = tid & 31;
    const int mw = wid >> 2, nw = wid & 3;
    const int row0 = blockIdx.x * 128;
    const int n0 = blockIdx.y * 128;

    float acc[4][4][4] = {};
    const uint32_t sbase = smem_u32(smem);
    auto abase = [&](int stage, int arr) {
        return sbase + (uint32_t)(((stage << 2) + arr) * STG_ELEMS * 2);
    };

    auto load_chunk = [&](int c, int stage) {
        const int k0 = c * BK;
        #pragma unroll
        for (int i = 0; i < 2; i++) {
            int idx = tid + i * 256;
            int r = idx >> 2, q = idx & 3;
            uint32_t doff = (uint32_t)(r * LDP + q * 8) * 2;
            int grow = row0 + r;
            int pa = (grow < M) ? 16 : 0;
            int ga = grow < M ? grow : (M - 1);
            cpa16(abase(stage, 0) + doff, Ah + (size_t)ga * K + k0 + q * 8, pa);
            cpa16(abase(stage, 1) + doff, Al + (size_t)ga * K + k0 + q * 8, pa);
            cpa16(abase(stage, 2) + doff, Bh + (size_t)(n0 + r) * K + k0 + q * 8, 16);
            cpa16(abase(stage, 3) + doff, Bl + (size_t)(n0 + r) * K + k0 + q * 8, 16);
        }
    };

    const int a_row_sel = lane & 15;
    const int a_k_sel   = (lane >> 4) * 8;
    const int b_row_sel = (lane & 7) + ((lane >> 4) << 3);
    const int b_k_sel   = ((lane >> 3) & 1) * 8;

    const int nchunks = K / BK;
    load_chunk(0, 0);
    asm volatile("cp.async.commit_group;" ::: "memory");

    for (int c = 0; c < nchunks; c++) {
        if (c + 1 < nchunks) load_chunk(c + 1, (c + 1) & 1);
        asm volatile("cp.async.commit_group;" ::: "memory");
        asm volatile("cp.async.wait_group 1;" ::: "memory");
        __syncthreads();
        const int st = c & 1;
        const uint32_t sAh = abase(st, 0), sAl = abase(st, 1);
        const uint32_t sBh = abase(st, 2), sBl = abase(st, 3);
        #pragma unroll
        for (int ks = 0; ks < 2; ks++) {
            const int koff = ks * 16;
            uint32_t ah[4][4], al[4][4];
            #pragma unroll
            for (int mi = 0; mi < 4; mi++) {
                uint32_t off = (uint32_t)((mw * 64 + mi * 16 + a_row_sel) * LDP
                                          + koff + a_k_sel) * 2;
                ldmx4(ah[mi], sAh + off);
                ldmx4(al[mi], sAl + off);
            }
            uint32_t bh[2][4], bl[2][4];
            #pragma unroll
            for (int p = 0; p < 2; p++) {
                uint32_t off = (uint32_t)((nw * 32 + p * 16 + b_row_sel) * LDP
                                          + koff + b_k_sel) * 2;
                ldmx4(bh[p], sBh + off);
                ldmx4(bl[p], sBl + off);
            }
            #pragma unroll
            for (int mi = 0; mi < 4; mi++) {
                #pragma unroll
                for (int ni = 0; ni < 4; ni++) {
                    uint32_t b0h = bh[ni >> 1][(ni & 1) * 2], b1h = bh[ni >> 1][(ni & 1) * 2 + 1];
                    uint32_t b0l = bl[ni >> 1][(ni & 1) * 2], b1l = bl[ni >> 1][(ni & 1) * 2 + 1];
                    mma_bf16(acc[mi][ni], ah[mi], b0h, b1h);
                    mma_bf16(acc[mi][ni], ah[mi], b0l, b1l);
                    mma_bf16(acc[mi][ni], al[mi], b0h, b1h);
                }
            }
        }
        __syncthreads();
    }

    const int mrow = row0 + mw * 64 + (lane >> 2);
    const int ncol = n0 + nw * 32 + (lane & 3) * 2;

    if (m3s) {  // fused scoring
        #pragma unroll
        for (int mi = 0; mi < 4; mi++) {
            int r_lo = mrow + mi * 16;
            int r_hi = r_lo + 8;
            float plo = 0.f, phi = 0.f;
            #pragma unroll
            for (int ni = 0; ni < 4; ni++) {
                int col = ncol + ni * 8;
                float m30 = __ldg(m3s + col), m31 = __ldg(m3s + col + 1);
                float b0 = __ldg(bias + col), b1 = __ldg(bias + col + 1);
                plo += fmaxf(acc[mi][ni][0] + b0, 0.f) * m30
                     + fmaxf(acc[mi][ni][1] + b1, 0.f) * m31;
                phi += fmaxf(acc[mi][ni][2] + b0, 0.f) * m30
                     + fmaxf(acc[mi][ni][3] + b1, 0.f) * m31;
            }
            plo += __shfl_xor_sync(0xffffffffu, plo, 1);
            plo += __shfl_xor_sync(0xffffffffu, plo, 2);
            phi += __shfl_xor_sync(0xffffffffu, phi, 1);
            phi += __shfl_xor_sync(0xffffffffu, phi, 2);
            if ((lane & 3) == 0) {
                if (r_lo < M) atomicAdd(sc + r_lo, plo);
                if (r_hi < M) atomicAdd(sc + r_hi, phi);
            }
        }
        return;
    }

    if (Ch) {  // relu + bf16 hi/lo split write (h1 producer)
        #pragma unroll
        for (int mi = 0; mi < 4; mi++) {
            int r_lo = mrow + mi * 16;
            int r_hi = r_lo + 8;
            #pragma unroll
            for (int ni = 0; ni < 4; ni++) {
                int col = ncol + ni * 8;
                float b0 = bias ? __ldg(bias + col) : 0.f;
                float b1 = bias ? __ldg(bias + col + 1) : 0.f;
                float v0 = fmaxf(acc[mi][ni][0] + b0, 0.f);
                float v1 = fmaxf(acc[mi][ni][1] + b1, 0.f);
                float v2 = fmaxf(acc[mi][ni][2] + b0, 0.f);
                float v3 = fmaxf(acc[mi][ni][3] + b1, 0.f);
                uint32_t hu, lu;
                if (r_lo < M) {
                    pack_hl(v0, v1, hu, lu);
                    *(uint32_t*)(Ch + (size_t)r_lo * Ncol + col) = hu;
                    *(uint32_t*)(Cl + (size_t)r_lo * Ncol + col) = lu;
                }
                if (r_hi < M) {
                    pack_hl(v2, v3, hu, lu);
                    *(uint32_t*)(Ch + (size_t)r_hi * Ncol + col) = hu;
                    *(uint32_t*)(Cl + (size_t)r_hi * Ncol + col) = lu;
                }
            }
        }
        return;
    }

    #pragma unroll
    for (int mi = 0; mi < 4; mi++) {
        int r_lo = mrow + mi * 16;
        int r_hi = r_lo + 8;
        #pragma unroll
        for (int ni = 0; ni < 4; ni++) {
            int col = ncol + ni * 8;
            float v0 = acc[mi][ni][0], v1 = acc[mi][ni][1];
            float v2 = acc[mi][ni][2], v3 = acc[mi][ni][3];
            if (relu) {
                v0 = fmaxf(v0, 0.f); v1 = fmaxf(v1, 0.f);
                v2 = fmaxf(v2, 0.f); v3 = fmaxf(v3, 0.f);
            }
            if (r_lo < M) *(float2*)(C + (size_t)r_lo * Ncol + col) = make_float2(v0, v1);
            if (r_hi < M) *(float2*)(C + (size_t)r_hi * Ncol + col) = make_float2(v2, v3);
        }
    }
}

// ---------------- launch -----------------------------------------------------
extern "C" void kernel_launch(void* const* d_in, const int* in_sizes, int n_in,
                              void* d_out, int out_size) {
    const int*   adjr[2] = {(const int*)d_in[0], (const int*)d_in[3]};
    const int*   adjc[2] = {(const int*)d_in[1], (const int*)d_in[4]};
    const float* adjv[2] = {(const float*)d_in[2], (const float*)d_in[5]};
    const float* w1 = (const float*)d_in[6];
    const float* m1 = (const float*)d_in[15];
    const float* b1 = (const float*)d_in[16];
    const float* m2 = (const float*)d_in[17];
    const float* b2 = (const float*)d_in[18];
    const float* m3 = (const float*)d_in[19];
    const float* b3 = (const float*)d_in[20];
    float* out = (float*)d_out;

    const int E = in_sizes[0];
    const int M = in_sizes[6] / HH;

    __nv_bfloat16 *xh, *xl, *h1h, *h1l, *wth, *wtl;
    float *gt, *csv;
    float (*gs)[NN];
    int *rp, *cnt, *csc;
    cudaGetSymbolAddress((void**)&xh,  g_xh);
    cudaGetSymbolAddress((void**)&xl,  g_xl);
    cudaGetSymbolAddress((void**)&gt,  g_t);
    cudaGetSymbolAddress((void**)&h1h, g_h1h);
    cudaGetSymbolAddress((void**)&h1l, g_h1l);
    cudaGetSymbolAddress((void**)&gs,  g_s);
    cudaGetSymbolAddress((void**)&rp,  g_rp);
    cudaGetSymbolAddress((void**)&cnt, g_cnt);
    cudaGetSymbolAddress((void**)&csc, g_cols);
    cudaGetSymbolAddress((void**)&csv, g_vals);
    cudaGetSymbolAddress((void**)&wth, g_wth);
    cudaGetSymbolAddress((void**)&wtl, g_wtl);

    cudaFuncSetAttribute(tc_gemm_kernel,
                         cudaFuncAttributeMaxDynamicSharedMemorySize, GEMM_SMEM);

    // launch #0: all weight conversions + cnt zeroing (one kernel)
    ConvSrcs cs;
    for (int i = 0; i < 8; i++) cs.p[i] = (const float*)d_in[7 + i];
    cs.p[8] = m1; cs.p[9] = m2;
    {
        int tot = (int)WT_TOTAL + NN;
        conv_all_kernel<<<(tot + 255) / 256, 256>>>(cs, wth, wtl, cnt);
    }

    const int warpBlocks = (int)(((long long)M * 32 + 255) / 256);
    const int eBlocks = (E + 255) / 256;
    const int nBlocks = (M + 255) / 256;
    const int mtiles = (M + 127) / 128;
    dim3 g_w(mtiles, 1);
    dim3 g_m(mtiles, 2);

    for (int b = 0; b < 2; b++) {
        if (b) zero_int_kernel<<<nBlocks, 256>>>(cnt, M);        // cnt reused
        hist_kernel<<<eBlocks, 256>>>(adjr[b], cnt, E);          // #1
        scan_kernel<<<1, 1024>>>(cnt, rp, cnt, M);               // #2 (rp + cursor)
        scatter_kernel<<<eBlocks, 256>>>(adjr[b], adjc[b], adjv[b], cnt, csc, csv,
                                         E, gs[b], b3, M);       // #3
        // layer 0: x = l2norm(relu(A @ w1)), split bf16
        spmm_csr_kernel<<<warpBlocks, 256>>>(rp, csc, csv, w1, xh, xl, M, 1);  // #4

        for (int L = 0; L <= 8; L++) {
            // MLP scoring (m1: split h1 producer; m2: fused scoring epilogue)
            tc_gemm_kernel<<<g_m, 256, GEMM_SMEM>>>(xh, xl, wth + WT_M1, wtl + WT_M1,
                                                    b1, nullptr, h1h, h1l,
                                                    M, HH, HD2, 1, nullptr, nullptr);  // #5
            tc_gemm_kernel<<<g_m, 256, GEMM_SMEM>>>(h1h, h1l, wth + WT_M2, wtl + WT_M2,
                                                    b2, nullptr, nullptr, nullptr,
                                                    M, HD2, HD2, 1, m3, gs[b]);
            if (L < 8) {
                tc_gemm_kernel<<<g_w, 256, GEMM_SMEM>>>(xh, xl, wth + WT_W(L), wtl + WT_W(L),
                                                        nullptr, gt, nullptr, nullptr,
                                                        M, HH, HH, 0, nullptr, nullptr);
                spmm_csr_kernel<<<warpBlocks, 256>>>(rp, csc, csv, gt, xh, xl, M,
                                                     (L + 1 < 8) ? 1 : 0);
            }
        }
    }

    mul_kernel<<<nBlocks, 256>>>(gs[0], gs[1], out, M);
}

// round 10
// speedup vs baseline: 2.7962x; 1.1197x over previous
#include <cuda_runtime.h>
#include <cuda_bf16.h>
#include <math.h>
#include <cstdint>

#define NN 100000
#define EE 1600000
#define HH 128
#define HD2 256

// ---------------- scratch (__device__ globals) -------------------------------
__device__ __nv_bfloat16 g_xh [(size_t)NN * HH];
__device__ __nv_bfloat16 g_xl [(size_t)NN * HH];
__device__ float         g_t  [(size_t)NN * HH];
__device__ __nv_bfloat16 g_h1h[(size_t)NN * HD2];
__device__ __nv_bfloat16 g_h1l[(size_t)NN * HD2];
__device__ float g_s[2][NN];
__device__ int   g_rp  [NN + 1];
__device__ int   g_cnt [NN];
__device__ int   g_cols[EE];
__device__ float g_vals[EE];

#define WT_W(i)  ((size_t)(i) * 16384)
#define WT_M1    ((size_t)8 * 16384)
#define WT_M2    (WT_M1 + 32768)
#define WT_TOTAL (WT_M2 + 65536)
__device__ __nv_bfloat16 g_wth[WT_TOTAL];
__device__ __nv_bfloat16 g_wtl[WT_TOTAL];

// ---------------- helpers ----------------------------------------------------
__device__ __forceinline__ uint32_t smem_u32(const void* p) {
    uint32_t a;
    asm("{ .reg .u64 t; cvta.to.shared.u64 t, %1; cvt.u32.u64 %0, t; }" : "=r"(a) : "l"(p));
    return a;
}
__device__ __forceinline__ void ldmx4(uint32_t* r, uint32_t addr) {
    asm volatile("ldmatrix.sync.aligned.m8n8.x4.shared.b16 {%0,%1,%2,%3}, [%4];"
                 : "=r"(r[0]), "=r"(r[1]), "=r"(r[2]), "=r"(r[3]) : "r"(addr));
}
__device__ __forceinline__ void mma_bf16(float* c, const uint32_t* a, uint32_t b0, uint32_t b1) {
    asm volatile(
        "mma.sync.aligned.m16n8k16.row.col.f32.bf16.bf16.f32 "
        "{%0,%1,%2,%3}, {%4,%5,%6,%7}, {%8,%9}, {%0,%1,%2,%3};"
        : "+f"(c[0]), "+f"(c[1]), "+f"(c[2]), "+f"(c[3])
        : "r"(a[0]), "r"(a[1]), "r"(a[2]), "r"(a[3]), "r"(b0), "r"(b1));
}
__device__ __forceinline__ void cpa16(uint32_t dst, const void* src, int nbytes) {
    asm volatile("cp.async.cg.shared.global [%0], [%1], 16, %2;"
                 :: "r"(dst), "l"(src), "r"(nbytes) : "memory");
}
__device__ __forceinline__ void pack_hl(float a, float b, uint32_t& hu, uint32_t& lu) {
    __nv_bfloat16 ha = __float2bfloat16(a), hb = __float2bfloat16(b);
    __nv_bfloat16 la = __float2bfloat16(a - __bfloat162float(ha));
    __nv_bfloat16 lb = __float2bfloat16(b - __bfloat162float(hb));
    hu = (uint32_t)__bfloat16_as_ushort(ha) | ((uint32_t)__bfloat16_as_ushort(hb) << 16);
    lu = (uint32_t)__bfloat16_as_ushort(la) | ((uint32_t)__bfloat16_as_ushort(lb) << 16);
}

// ---------------- preprocessing ------------------------------------------------
struct ConvSrcs { const float* p[10]; };

__global__ void conv_all_kernel(ConvSrcs srcs, __nv_bfloat16* __restrict__ oh,
                                __nv_bfloat16* __restrict__ ol, int* __restrict__ cnt) {
    int gid = blockIdx.x * blockDim.x + threadIdx.x;
    if (gid < (int)WT_TOTAL) {
        const float* W; int local, K, Ncol;
        if (gid < 131072)               { W = srcs.p[gid >> 14]; local = gid & 16383;            K = HH;  Ncol = HH;  }
        else if (gid < 131072 + 32768)  { W = srcs.p[8];         local = gid - 131072;           K = HH;  Ncol = HD2; }
        else                            { W = srcs.p[9];         local = gid - (131072 + 32768); K = HD2; Ncol = HD2; }
        int n = local / K, k = local - n * K;
        float v = W[(size_t)k * Ncol + n];
        __nv_bfloat16 h = __float2bfloat16(v);
        oh[gid] = h;
        ol[gid] = __float2bfloat16(v - __bfloat162float(h));
    } else {
        int j = gid - (int)WT_TOTAL;
        if (j < NN) cnt[j] = 0;
    }
}

__global__ void zero_int_kernel(int* __restrict__ p, int n) {
    int i = blockIdx.x * blockDim.x + threadIdx.x;
    if (i < n) p[i] = 0;
}

__global__ void hist_kernel(const int* __restrict__ rows, int* __restrict__ cnt, int nE) {
    int e = blockIdx.x * blockDim.x + threadIdx.x;
    if (e < nE) atomicAdd(&cnt[rows[e]], 1);
}

__global__ void scan_kernel(const int* __restrict__ cnt, int* __restrict__ rp,
                            int* __restrict__ cur, int n) {
    __shared__ int sdata[1024];
    __shared__ int carry;
    int tid = threadIdx.x;
    if (tid == 0) { carry = 0; rp[0] = 0; }
    __syncthreads();
    for (int base = 0; base < n; base += 1024) {
        int i = base + tid;
        int v = (i < n) ? cnt[i] : 0;
        sdata[tid] = v;
        __syncthreads();
        #pragma unroll
        for (int o = 1; o < 1024; o <<= 1) {
            int t = sdata[tid];
            if (tid >= o) t += sdata[tid - o];
            __syncthreads();
            sdata[tid] = t;
            __syncthreads();
        }
        if (i < n) {
            int incl = carry + sdata[tid];
            rp[i + 1] = incl;
            cur[i] = incl - v;
        }
        __syncthreads();
        if (tid == 0) carry += sdata[1023];
        __syncthreads();
    }
}

__global__ void scatter_kernel(const int* __restrict__ rows, const int* __restrict__ cols,
                               const float* __restrict__ vals, int* __restrict__ cur,
                               int* __restrict__ cs, float* __restrict__ vs, int nE,
                               float* __restrict__ s, const float* __restrict__ b3, int M) {
    int e = blockIdx.x * blockDim.x + threadIdx.x;
    if (e < M) s[e] = 9.0f * b3[0];
    if (e >= nE) return;
    int pos = atomicAdd(&cur[rows[e]], 1);
    cs[pos] = cols[e];
    vs[pos] = vals[e];
}

// ---------------- CSR SpMM fused relu(+norm) -> split bf16 -------------------
__global__ void spmm_csr_kernel(const int* __restrict__ rp, const int* __restrict__ cs,
                                const float* __restrict__ vs, const float* __restrict__ xin,
                                __nv_bfloat16* __restrict__ xh, __nv_bfloat16* __restrict__ xl,
                                int M, int do_norm) {
    long long idx = (long long)blockIdx.x * blockDim.x + threadIdx.x;
    int row = (int)(idx >> 5);
    if (row >= M) return;
    int lane = (int)(idx & 31);
    int s = __ldg(rp + row), e = __ldg(rp + row + 1);
    float ax = 0.f, ay = 0.f, az = 0.f, aw = 0.f;
    for (int j = s; j < e; j++) {
        int c = __ldg(cs + j);
        float v = __ldg(vs + j);
        float4 xv = *(const float4*)(xin + (size_t)c * HH + lane * 4);
        ax += v * xv.x; ay += v * xv.y; az += v * xv.z; aw += v * xv.w;
    }
    ax = fmaxf(ax, 0.f); ay = fmaxf(ay, 0.f);
    az = fmaxf(az, 0.f); aw = fmaxf(aw, 0.f);
    if (do_norm) {
        float ss = ax * ax + ay * ay + az * az + aw * aw;
        #pragma unroll
        for (int o = 16; o; o >>= 1) ss += __shfl_xor_sync(0xffffffffu, ss, o);
        float inv = 1.0f / fmaxf(sqrtf(ss), 1e-12f);
        ax *= inv; ay *= inv; az *= inv; aw *= inv;
    }
    uint2 hv, lv;
    pack_hl(ax, ay, hv.x, lv.x);
    pack_hl(az, aw, hv.y, lv.y);
    size_t off = (size_t)row * HH + lane * 4;
    *(uint2*)(xh + off) = hv;
    *(uint2*)(xl + off) = lv;
}

__global__ void mul_kernel(const float* __restrict__ a, const float* __restrict__ b,
                           float* __restrict__ out, int M) {
    int i = blockIdx.x * blockDim.x + threadIdx.x;
    if (i < M) out[i] = a[i] * b[i];
}

// ---------------- pipelined mma.sync GEMM -------------------------------------
// 3-term Markidis bf16 split. BM=128,BN=128,BK=32; 8 warps (2x4).
// 4-stage cp.async pipeline, one __syncthreads per chunk, frag double-buffer.
// mode 0 (fused m1+w): blockIdx.y < ny1 -> B1 (m1), relu+bias1, split write Ch/Cl [Ncol1]
//                      blockIdx.y ==ny1 -> B2 (w), raw fp32 write C2 [Ncol2]
// mode 1 (m2 scoring): B1 (m2), epilogue relu(acc+bias1) dot m3s -> atomicAdd(sc)
#define BK 32
#define LDP 40
#define STG_ELEMS (128 * LDP)
#define NSTG 4
#define GEMM_SMEM (NSTG * 4 * STG_ELEMS * 2)   // 163840 B

__global__ void __launch_bounds__(256, 1) tc_gemm_kernel(
    const __nv_bfloat16* __restrict__ Ah, const __nv_bfloat16* __restrict__ Al,
    const __nv_bfloat16* __restrict__ B1h, const __nv_bfloat16* __restrict__ B1l,
    int ny1, int Ncol1, const float* __restrict__ bias1,
    const __nv_bfloat16* __restrict__ B2h, const __nv_bfloat16* __restrict__ B2l,
    float* __restrict__ C2, int Ncol2,
    __nv_bfloat16* __restrict__ Ch, __nv_bfloat16* __restrict__ Cl,
    const float* __restrict__ m3s, float* __restrict__ sc,
    int M, int K, int mode)
{
    extern __shared__ __align__(16) uint16_t smem[];
    const int tid = threadIdx.x;
    const int wid = tid >> 5, lane = tid & 31;
    const int mw = wid >> 2, nw = wid & 3;
    const int row0 = blockIdx.x * 128;
    const bool isW = (mode == 0) && ((int)blockIdx.y == ny1);
    const __nv_bfloat16* Bh = isW ? B2h : B1h;
    const __nv_bfloat16* Bl = isW ? B2l : B1l;
    const int n0 = isW ? 0 : blockIdx.y * 128;

    float acc[4][4][4] = {};
    const uint32_t sbase = smem_u32(smem);
    auto abase = [&](int stage, int arr) {
        return sbase + (uint32_t)(((stage << 2) + arr) * STG_ELEMS * 2);
    };

    auto load_chunk = [&](int c, int stage) {
        const int k0 = c * BK;
        #pragma unroll
        for (int i = 0; i < 2; i++) {
            int idx = tid + i * 256;
            int r = idx >> 2, q = idx & 3;
            uint32_t doff = (uint32_t)(r * LDP + q * 8) * 2;
            int grow = row0 + r;
            int pa = (grow < M) ? 16 : 0;
            int ga = grow < M ? grow : (M - 1);
            cpa16(abase(stage, 0) + doff, Ah + (size_t)ga * K + k0 + q * 8, pa);
            cpa16(abase(stage, 1) + doff, Al + (size_t)ga * K + k0 + q * 8, pa);
            cpa16(abase(stage, 2) + doff, Bh + (size_t)(n0 + r) * K + k0 + q * 8, 16);
            cpa16(abase(stage, 3) + doff, Bl + (size_t)(n0 + r) * K + k0 + q * 8, 16);
        }
    };

    const int a_row_sel = lane & 15;
    const int a_k_sel   = (lane >> 4) * 8;
    const int b_row_sel = (lane & 7) + ((lane >> 4) << 3);
    const int b_k_sel   = ((lane >> 3) & 1) * 8;

    uint32_t ah[2][4][4], al[2][4][4], bh[2][2][4], bl[2][2][4];
    auto load_frags = [&](int buf, uint32_t sAh, uint32_t sAl, uint32_t sBh,
                          uint32_t sBl, int koff) {
        #pragma unroll
        for (int mi = 0; mi < 4; mi++) {
            uint32_t off = (uint32_t)((mw * 64 + mi * 16 + a_row_sel) * LDP
                                      + koff + a_k_sel) * 2;
            ldmx4(ah[buf][mi], sAh + off);
            ldmx4(al[buf][mi], sAl + off);
        }
        #pragma unroll
        for (int p = 0; p < 2; p++) {
            uint32_t off = (uint32_t)((nw * 32 + p * 16 + b_row_sel) * LDP
                                      + koff + b_k_sel) * 2;
            ldmx4(bh[buf][p], sBh + off);
            ldmx4(bl[buf][p], sBl + off);
        }
    };
    auto run_mmas = [&](int buf) {
        #pragma unroll
        for (int mi = 0; mi < 4; mi++) {
            #pragma unroll
            for (int ni = 0; ni < 4; ni++) {
                uint32_t b0h = bh[buf][ni >> 1][(ni & 1) * 2];
                uint32_t b1h = bh[buf][ni >> 1][(ni & 1) * 2 + 1];
                uint32_t b0l = bl[buf][ni >> 1][(ni & 1) * 2];
                uint32_t b1l = bl[buf][ni >> 1][(ni & 1) * 2 + 1];
                mma_bf16(acc[mi][ni], ah[buf][mi], b0h, b1h);
                mma_bf16(acc[mi][ni], ah[buf][mi], b0l, b1l);
                mma_bf16(acc[mi][ni], al[buf][mi], b0h, b1h);
            }
        }
    };

    const int nchunks = K / BK;
    load_chunk(0, 0);
    asm volatile("cp.async.commit_group;" ::: "memory");
    if (nchunks > 1) load_chunk(1, 1);
    asm volatile("cp.async.commit_group;" ::: "memory");

    for (int c = 0; c < nchunks; c++) {
        if (c + 2 < nchunks) load_chunk(c + 2, (c + 2) & (NSTG - 1));
        asm volatile("cp.async.commit_group;" ::: "memory");
        asm volatile("cp.async.wait_group 2;" ::: "memory");
        __syncthreads();
        const int st = c & (NSTG - 1);
        const uint32_t sAh = abase(st, 0), sAl = abase(st, 1);
        const uint32_t sBh = abase(st, 2), sBl = abase(st, 3);
        load_frags(0, sAh, sAl, sBh, sBl, 0);
        load_frags(1, sAh, sAl, sBh, sBl, 16);
        run_mmas(0);
        run_mmas(1);
    }

    const int mrow = row0 + mw * 64 + (lane >> 2);
    const int ncol = nw * 32 + (lane & 3) * 2;   // local within 128-tile

    if (mode == 1) {  // fused scoring
        #pragma unroll
        for (int mi = 0; mi < 4; mi++) {
            int r_lo = mrow + mi * 16;
            int r_hi = r_lo + 8;
            float plo = 0.f, phi = 0.f;
            #pragma unroll
            for (int ni = 0; ni < 4; ni++) {
                int col = n0 + ncol + ni * 8;
                float m30 = __ldg(m3s + col), m31 = __ldg(m3s + col + 1);
                float b0 = __ldg(bias1 + col), b1 = __ldg(bias1 + col + 1);
                plo += fmaxf(acc[mi][ni][0] + b0, 0.f) * m30
                     + fmaxf(acc[mi][ni][1] + b1, 0.f) * m31;
                phi += fmaxf(acc[mi][ni][2] + b0, 0.f) * m30
                     + fmaxf(acc[mi][ni][3] + b1, 0.f) * m31;
            }
            plo += __shfl_xor_sync(0xffffffffu, plo, 1);
            plo += __shfl_xor_sync(0xffffffffu, plo, 2);
            phi += __shfl_xor_sync(0xffffffffu, phi, 1);
            phi += __shfl_xor_sync(0xffffffffu, phi, 2);
            if ((lane & 3) == 0) {
                if (r_lo < M) atomicAdd(sc + r_lo, plo);
                if (r_hi < M) atomicAdd(sc + r_hi, phi);
            }
        }
        return;
    }

    if (!isW) {  // m1 part: relu + bf16 hi/lo split write
        #pragma unroll
        for (int mi = 0; mi < 4; mi++) {
            int r_lo = mrow + mi * 16;
            int r_hi = r_lo + 8;
            #pragma unroll
            for (int ni = 0; ni < 4; ni++) {
                int col = n0 + ncol + ni * 8;
                float b0 = __ldg(bias1 + col), b1 = __ldg(bias1 + col + 1);
                float v0 = fmaxf(acc[mi][ni][0] + b0, 0.f);
                float v1 = fmaxf(acc[mi][ni][1] + b1, 0.f);
                float v2 = fmaxf(acc[mi][ni][2] + b0, 0.f);
                float v3 = fmaxf(acc[mi][ni][3] + b1, 0.f);
                uint32_t hu, lu;
                if (r_lo < M) {
                    pack_hl(v0, v1, hu, lu);
                    *(uint32_t*)(Ch + (size_t)r_lo * Ncol1 + col) = hu;
                    *(uint32_t*)(Cl + (size_t)r_lo * Ncol1 + col) = lu;
                }
                if (r_hi < M) {
                    pack_hl(v2, v3, hu, lu);
                    *(uint32_t*)(Ch + (size_t)r_hi * Ncol1 + col) = hu;
                    *(uint32_t*)(Cl + (size_t)r_hi * Ncol1 + col) = lu;
                }
            }
        }
        return;
    }

    // w part: raw fp32 write to C2
    #pragma unroll
    for (int mi = 0; mi < 4; mi++) {
        int r_lo = mrow + mi * 16;
        int r_hi = r_lo + 8;
        #pragma unroll
        for (int ni = 0; ni < 4; ni++) {
            int col = ncol + ni * 8;
            if (r_lo < M) *(float2*)(C2 + (size_t)r_lo * Ncol2 + col) =
                make_float2(acc[mi][ni][0], acc[mi][ni][1]);
            if (r_hi < M) *(float2*)(C2 + (size_t)r_hi * Ncol2 + col) =
                make_float2(acc[mi][ni][2], acc[mi][ni][3]);
        }
    }
}

// ---------------- launch -----------------------------------------------------
extern "C" void kernel_launch(void* const* d_in, const int* in_sizes, int n_in,
                              void* d_out, int out_size) {
    const int*   adjr[2] = {(const int*)d_in[0], (const int*)d_in[3]};
    const int*   adjc[2] = {(const int*)d_in[1], (const int*)d_in[4]};
    const float* adjv[2] = {(const float*)d_in[2], (const float*)d_in[5]};
    const float* w1 = (const float*)d_in[6];
    const float* m1 = (const float*)d_in[15];
    const float* b1 = (const float*)d_in[16];
    const float* m2 = (const float*)d_in[17];
    const float* b2 = (const float*)d_in[18];
    const float* m3 = (const float*)d_in[19];
    const float* b3 = (const float*)d_in[20];
    float* out = (float*)d_out;

    const int E = in_sizes[0];
    const int M = in_sizes[6] / HH;

    __nv_bfloat16 *xh, *xl, *h1h, *h1l, *wth, *wtl;
    float *gt, *csv;
    float (*gs)[NN];
    int *rp, *cnt, *csc;
    cudaGetSymbolAddress((void**)&xh,  g_xh);
    cudaGetSymbolAddress((void**)&xl,  g_xl);
    cudaGetSymbolAddress((void**)&gt,  g_t);
    cudaGetSymbolAddress((void**)&h1h, g_h1h);
    cudaGetSymbolAddress((void**)&h1l, g_h1l);
    cudaGetSymbolAddress((void**)&gs,  g_s);
    cudaGetSymbolAddress((void**)&rp,  g_rp);
    cudaGetSymbolAddress((void**)&cnt, g_cnt);
    cudaGetSymbolAddress((void**)&csc, g_cols);
    cudaGetSymbolAddress((void**)&csv, g_vals);
    cudaGetSymbolAddress((void**)&wth, g_wth);
    cudaGetSymbolAddress((void**)&wtl, g_wtl);

    cudaFuncSetAttribute(tc_gemm_kernel,
                         cudaFuncAttributeMaxDynamicSharedMemorySize, GEMM_SMEM);

    ConvSrcs cs;
    for (int i = 0; i < 8; i++) cs.p[i] = (const float*)d_in[7 + i];
    cs.p[8] = m1; cs.p[9] = m2;
    {
        int tot = (int)WT_TOTAL + NN;
        conv_all_kernel<<<(tot + 255) / 256, 256>>>(cs, wth, wtl, cnt);
    }

    const int warpBlocks = (int)(((long long)M * 32 + 255) / 256);
    const int eBlocks = (E + 255) / 256;
    const int nBlocks = (M + 255) / 256;
    const int mtiles = (M + 127) / 128;

    for (int b = 0; b < 2; b++) {
        if (b) zero_int_kernel<<<nBlocks, 256>>>(cnt, M);
        hist_kernel<<<eBlocks, 256>>>(adjr[b], cnt, E);
        scan_kernel<<<1, 1024>>>(cnt, rp, cnt, M);
        scatter_kernel<<<eBlocks, 256>>>(adjr[b], adjc[b], adjv[b], cnt, csc, csv,
                                         E, gs[b], b3, M);
        spmm_csr_kernel<<<warpBlocks, 256>>>(rp, csc, csv, w1, xh, xl, M, 1);

        for (int L = 0; L <= 8; L++) {
            // fused m1 (+ wL when L<8): A = x
            dim3 gf(mtiles, (L < 8) ? 3 : 2);
            tc_gemm_kernel<<<gf, 256, GEMM_SMEM>>>(
                xh, xl,
                wth + WT_M1, wtl + WT_M1, 2, HD2, b1,
                (L < 8) ? wth + WT_W(L) : nullptr,
                (L < 8) ? wtl + WT_W(L) : nullptr, gt, HH,
                h1h, h1l, nullptr, nullptr, M, HH, 0);
            // m2 scoring
            dim3 gm(mtiles, 2);
            tc_gemm_kernel<<<gm, 256, GEMM_SMEM>>>(
                h1h, h1l,
                wth + WT_M2, wtl + WT_M2, 2, HD2, b2,
                nullptr, nullptr, nullptr, 0,
                nullptr, nullptr, m3, gs[b], M, HD2, 1);
            if (L < 8)
                spmm_csr_kernel<<<warpBlocks, 256>>>(rp, csc, csv, gt, xh, xl, M,
                                                     (L + 1 < 8) ? 1 : 0);
        }
    }

    mul_kernel<<<nBlocks, 256>>>(gs[0], gs[1], out, M);
}